// round 5
// baseline (speedup 1.0000x reference)
#include <cuda_runtime.h>
#include <cuda_bf16.h>
#include <math.h>

// Problem constants
static constexpr int Bn   = 8;
static constexpr int Cn   = 64;
static constexpr int Hn   = 256;
static constexpr int Wn   = 256;
static constexpr int HWn  = Hn * Wn;          // 65536
static constexpr int CHWn = Cn * HWn;         // 4194304
static constexpr long long TOTALn = (long long)Bn * CHWn;  // 33554432

// Scratch (device globals: allocation-free contract)
__device__ float g_q[33554432];
__device__ float g_k[33554432];
__device__ float g_v[33554432];
__device__ float g_attn[33554432];

// ---------------------------------------------------------------------------
// Kernel A: fused 1x1 conv for q, k, v.
// Grid: (HW/64, B). Block: 256 threads. Tile: 64 pixels x 64 out-channels.
// y[o,p] = sum_c W[o,c] * x[c,p] + b[o]
// ---------------------------------------------------------------------------
__global__ void __launch_bounds__(256) qkv_kernel(
    const float* __restrict__ x,
    const float* __restrict__ Wq, const float* __restrict__ bq,
    const float* __restrict__ Wk, const float* __restrict__ bk,
    const float* __restrict__ Wv, const float* __restrict__ bv)
{
    __shared__ float Xs[64][68];    // [c][p], padded for conflict-free float4
    __shared__ float WsT[64][68];   // [k][o], transposed W, padded

    const int t  = threadIdx.x;
    const int b  = blockIdx.y;
    const int p0 = blockIdx.x * 64;
    const int tx = t & 15;          // pixel group
    const int ty = t >> 4;          // out-channel group

    // Load X tile [64c x 64p] (float4, fully coalesced)
    {
        const float* xb = x + (size_t)b * CHWn + p0;
        const int row  = t >> 4;          // 0..15
        const int col4 = (t & 15) * 4;    // 0..60
        #pragma unroll
        for (int c0 = 0; c0 < 64; c0 += 16) {
            float4 v4 = *reinterpret_cast<const float4*>(
                xb + (size_t)(c0 + row) * HWn + col4);
            *reinterpret_cast<float4*>(&Xs[c0 + row][col4]) = v4;
        }
    }

    const float* Wmats[3] = {Wq, Wk, Wv};
    const float* biases[3] = {bq, bk, bv};
    float* outs[3] = {g_q, g_k, g_v};

    for (int m = 0; m < 3; m++) {
        __syncthreads();  // protect WsT reuse across matrices (and Xs on m==0)
        // Stage W transposed: WsT[c][o] = W[o][c]
        const float* Wsrc = Wmats[m];
        for (int idx = t; idx < 4096; idx += 256)
            WsT[idx & 63][idx >> 6] = Wsrc[idx];
        __syncthreads();

        float acc[4][4] = {};
        #pragma unroll
        for (int k = 0; k < 64; k++) {
            float4 wv = *reinterpret_cast<const float4*>(&WsT[k][ty * 4]);
            float4 xv = *reinterpret_cast<const float4*>(&Xs[k][tx * 4]);
            float wa[4] = {wv.x, wv.y, wv.z, wv.w};
            float xa[4] = {xv.x, xv.y, xv.z, xv.w};
            #pragma unroll
            for (int oo = 0; oo < 4; oo++)
                #pragma unroll
                for (int pp = 0; pp < 4; pp++)
                    acc[oo][pp] += wa[oo] * xa[pp];
        }

        const float* bsrc = biases[m];
        float* dst = outs[m] + (size_t)b * CHWn + p0;
        #pragma unroll
        for (int oo = 0; oo < 4; oo++) {
            const int o = ty * 4 + oo;
            const float bb = bsrc[o];
            float4 r;
            r.x = acc[oo][0] + bb;
            r.y = acc[oo][1] + bb;
            r.z = acc[oo][2] + bb;
            r.w = acc[oo][3] + bb;
            *reinterpret_cast<float4*>(dst + (size_t)o * HWn + tx * 4) = r;
        }
    }
}

// ---------------------------------------------------------------------------
// Kernel B: attn[z,i,j] = sum_h q[z,h,i] * k[z,h,j]   (z = b*64 + c)
// Both operands are K-major in memory -> direct coalesced loads, no transpose.
// Grid: (2, 2, 512). Block: 256 threads. Tile 128x128, K-step 8, 8x8/thread.
// ---------------------------------------------------------------------------
__global__ void __launch_bounds__(256) gemm_qtk_kernel()
{
    const int z  = blockIdx.z;
    const float* A  = g_q    + (size_t)z * HWn;   // [k=256][m=256]
    const float* Bm = g_k    + (size_t)z * HWn;   // [k=256][n=256]
    float*       Cm = g_attn + (size_t)z * HWn;   // [m=256][n=256]
    const int m0 = blockIdx.x * 128;
    const int n0 = blockIdx.y * 128;

    __shared__ float As[8][128];
    __shared__ float Bs[8][128];

    const int t  = threadIdx.x;
    const int lk = t >> 5;           // 0..7
    const int lm = (t & 31) * 4;     // 0..124
    const int tx = t & 15;
    const int ty = t >> 4;
    const int i0 = ty * 8;
    const int j0 = tx * 8;

    float acc[8][8] = {};

    for (int k0 = 0; k0 < 256; k0 += 8) {
        float4 av = *reinterpret_cast<const float4*>(A  + (size_t)(k0 + lk) * Wn + m0 + lm);
        float4 bv = *reinterpret_cast<const float4*>(Bm + (size_t)(k0 + lk) * Wn + n0 + lm);
        __syncthreads();
        *reinterpret_cast<float4*>(&As[lk][lm]) = av;
        *reinterpret_cast<float4*>(&Bs[lk][lm]) = bv;
        __syncthreads();

        #pragma unroll
        for (int kk = 0; kk < 8; kk++) {
            float a[8], bb[8];
            *reinterpret_cast<float4*>(&a[0])  = *reinterpret_cast<const float4*>(&As[kk][i0]);
            *reinterpret_cast<float4*>(&a[4])  = *reinterpret_cast<const float4*>(&As[kk][i0 + 4]);
            *reinterpret_cast<float4*>(&bb[0]) = *reinterpret_cast<const float4*>(&Bs[kk][j0]);
            *reinterpret_cast<float4*>(&bb[4]) = *reinterpret_cast<const float4*>(&Bs[kk][j0 + 4]);
            #pragma unroll
            for (int ii = 0; ii < 8; ii++)
                #pragma unroll
                for (int jj = 0; jj < 8; jj++)
                    acc[ii][jj] += a[ii] * bb[jj];
        }
    }

    #pragma unroll
    for (int ii = 0; ii < 8; ii++) {
        float4* dst = reinterpret_cast<float4*>(Cm + (size_t)(m0 + i0 + ii) * Wn + n0 + j0);
        dst[0] = make_float4(acc[ii][0], acc[ii][1], acc[ii][2], acc[ii][3]);
        dst[1] = make_float4(acc[ii][4], acc[ii][5], acc[ii][6], acc[ii][7]);
    }
}

// ---------------------------------------------------------------------------
// Kernel C: softmax over the CHANNEL axis.
// One thread per (b, i, j): 64 channel values (stride HW) held in registers.
// ---------------------------------------------------------------------------
__global__ void __launch_bounds__(256) softmax_channel_kernel()
{
    const int idx = blockIdx.x * 256 + threadIdx.x;   // 0 .. B*HW-1
    const int b   = idx >> 16;
    const int ij  = idx & 65535;
    float* base = g_attn + (size_t)b * CHWn + ij;

    float v[64];
    float mx = -INFINITY;
    #pragma unroll
    for (int c = 0; c < 64; c++) {
        v[c] = base[(size_t)c * HWn];
        mx = fmaxf(mx, v[c]);
    }
    float s = 0.0f;
    #pragma unroll
    for (int c = 0; c < 64; c++) {
        v[c] = expf(v[c] - mx);
        s += v[c];
    }
    const float inv = 1.0f / s;
    #pragma unroll
    for (int c = 0; c < 64; c++)
        base[(size_t)c * HWn] = v[c] * inv;
}

// ---------------------------------------------------------------------------
// Kernel D: out[z,i,j] = sum_m attn[z,i,m] * v[z,m,j]
// A is row-major over (i,m) -> transpose into padded smem. B is already k-major.
// ---------------------------------------------------------------------------
__global__ void __launch_bounds__(256) gemm_av_kernel(float* __restrict__ out)
{
    const int z  = blockIdx.z;
    const float* A  = g_attn + (size_t)z * HWn;  // [i=256][m=256]
    const float* Bm = g_v    + (size_t)z * HWn;  // [m=256][j=256]
    float*       Cm = out    + (size_t)z * HWn;
    const int m0 = blockIdx.x * 128;  // i tile
    const int n0 = blockIdx.y * 128;  // j tile

    __shared__ float As[8][132];      // [k][i], padded to kill transpose conflicts
    __shared__ float Bs[8][128];

    const int t  = threadIdx.x;
    const int ai  = t >> 1;           // 0..127 (i within tile)
    const int ak4 = (t & 1) * 4;      // 0 or 4 (k within tile)
    const int lk = t >> 5;
    const int lm = (t & 31) * 4;
    const int tx = t & 15;
    const int ty = t >> 4;
    const int i0 = ty * 8;
    const int j0 = tx * 8;

    float acc[8][8] = {};

    for (int k0 = 0; k0 < 256; k0 += 8) {
        float4 av = *reinterpret_cast<const float4*>(A  + (size_t)(m0 + ai) * Wn + k0 + ak4);
        float4 bv = *reinterpret_cast<const float4*>(Bm + (size_t)(k0 + lk) * Wn + n0 + lm);
        __syncthreads();
        As[ak4 + 0][ai] = av.x;
        As[ak4 + 1][ai] = av.y;
        As[ak4 + 2][ai] = av.z;
        As[ak4 + 3][ai] = av.w;
        *reinterpret_cast<float4*>(&Bs[lk][lm]) = bv;
        __syncthreads();

        #pragma unroll
        for (int kk = 0; kk < 8; kk++) {
            float a[8], bb[8];
            *reinterpret_cast<float4*>(&a[0])  = *reinterpret_cast<const float4*>(&As[kk][i0]);
            *reinterpret_cast<float4*>(&a[4])  = *reinterpret_cast<const float4*>(&As[kk][i0 + 4]);
            *reinterpret_cast<float4*>(&bb[0]) = *reinterpret_cast<const float4*>(&Bs[kk][j0]);
            *reinterpret_cast<float4*>(&bb[4]) = *reinterpret_cast<const float4*>(&Bs[kk][j0 + 4]);
            #pragma unroll
            for (int ii = 0; ii < 8; ii++)
                #pragma unroll
                for (int jj = 0; jj < 8; jj++)
                    acc[ii][jj] += a[ii] * bb[jj];
        }
    }

    #pragma unroll
    for (int ii = 0; ii < 8; ii++) {
        float4* dst = reinterpret_cast<float4*>(Cm + (size_t)(m0 + i0 + ii) * Wn + n0 + j0);
        dst[0] = make_float4(acc[ii][0], acc[ii][1], acc[ii][2], acc[ii][3]);
        dst[1] = make_float4(acc[ii][4], acc[ii][5], acc[ii][6], acc[ii][7]);
    }
}

// ---------------------------------------------------------------------------
// Launch
// ---------------------------------------------------------------------------
extern "C" void kernel_launch(void* const* d_in, const int* in_sizes, int n_in,
                              void* d_out, int out_size)
{
    const float* x  = (const float*)d_in[0];
    const float* Wq = (const float*)d_in[1];
    const float* bq = (const float*)d_in[2];
    const float* Wk = (const float*)d_in[3];
    const float* bk = (const float*)d_in[4];
    const float* Wv = (const float*)d_in[5];
    const float* bv = (const float*)d_in[6];
    float* out = (float*)d_out;

    // 1) q,k,v = 1x1 conv(x)
    qkv_kernel<<<dim3(HWn / 64, Bn), 256>>>(x, Wq, bq, Wk, bk, Wv, bv);

    // 2) attn logits: q^T k per (b,c) — 512 x (256^3) GEMMs
    gemm_qtk_kernel<<<dim3(2, 2, Bn * Cn), 256>>>();

    // 3) softmax over channels
    softmax_channel_kernel<<<(Bn * HWn) / 256, 256>>>();

    // 4) out = attn @ v per (b,c)
    gemm_av_kernel<<<dim3(2, 2, Bn * Cn), 256>>>(out);
}

// round 8
// speedup vs baseline: 1.4686x; 1.4686x over previous
#include <cuda_runtime.h>
#include <cuda_bf16.h>
#include <math.h>
#include <stdint.h>

// ---------------------------------------------------------------------------
// Problem constants
// ---------------------------------------------------------------------------
static constexpr int Bn = 8, Cn = 64, Hn = 256, Wn = 256;
static constexpr int HWn  = Hn * Wn;       // 65536
static constexpr int CHWn = Cn * HWn;      // 4194304
static constexpr int NZ   = Bn * Cn;       // 512
static constexpr int NTOT = 33554432;      // B*C*H*W

// ---------------------------------------------------------------------------
// Scratch (device globals: allocation-free contract)
// q,k,v bf16 hi/lo in natural [z][h][w] layout (h = contraction axis of q^T k,
// so these are already K-major for ldmatrix.trans).
// ---------------------------------------------------------------------------
__device__ __nv_bfloat16 g_qh[NTOT], g_ql[NTOT];
__device__ __nv_bfloat16 g_kh[NTOT], g_kl[NTOT];
__device__ __nv_bfloat16 g_vh[NTOT], g_vl[NTOT];
__device__ float         g_attn[NTOT];                 // fp32 logits [z][i][j]
__device__ __nv_bfloat16 g_ah[NTOT], g_al[NTOT];       // softmaxed attn split

// ---------------------------------------------------------------------------
// PTX helpers — sm_80-era features only (compile clean at .target sm_103)
// ---------------------------------------------------------------------------
__device__ __forceinline__ uint32_t smem_to_u32(const void* p) {
    uint32_t a;
    asm("{ .reg .u64 t; cvta.to.shared.u64 t, %1; cvt.u32.u64 %0, t; }"
        : "=r"(a) : "l"(p));
    return a;
}

__device__ __forceinline__ void cp16(uint32_t s, const void* g) {
    asm volatile("cp.async.cg.shared.global [%0], [%1], 16;"
                 :: "r"(s), "l"(g) : "memory");
}
__device__ __forceinline__ void cp_commit() {
    asm volatile("cp.async.commit_group;" ::: "memory");
}
template <int N>
__device__ __forceinline__ void cp_wait() {
    asm volatile("cp.async.wait_group %0;" :: "n"(N) : "memory");
}

__device__ __forceinline__ void ldsm_x4(uint32_t* r, uint32_t addr) {
    asm volatile("ldmatrix.sync.aligned.m8n8.x4.shared.b16 {%0,%1,%2,%3}, [%4];"
                 : "=r"(r[0]), "=r"(r[1]), "=r"(r[2]), "=r"(r[3]) : "r"(addr));
}
__device__ __forceinline__ void ldsm_x4_t(uint32_t* r, uint32_t addr) {
    asm volatile("ldmatrix.sync.aligned.m8n8.x4.trans.shared.b16 {%0,%1,%2,%3}, [%4];"
                 : "=r"(r[0]), "=r"(r[1]), "=r"(r[2]), "=r"(r[3]) : "r"(addr));
}

__device__ __forceinline__ void mma16816(float* c, const uint32_t* a, const uint32_t* b) {
    asm volatile(
        "mma.sync.aligned.m16n8k16.row.col.f32.bf16.bf16.f32 "
        "{%0,%1,%2,%3}, {%4,%5,%6,%7}, {%8,%9}, {%0,%1,%2,%3};"
        : "+f"(c[0]), "+f"(c[1]), "+f"(c[2]), "+f"(c[3])
        : "r"(a[0]), "r"(a[1]), "r"(a[2]), "r"(a[3]), "r"(b[0]), "r"(b[1]));
}

__device__ __forceinline__ void split_bf16(float x, __nv_bfloat16& hi, __nv_bfloat16& lo) {
    hi = __float2bfloat16(x);
    lo = __float2bfloat16(x - __bfloat162float(hi));
}

// ---------------------------------------------------------------------------
// Kernel A: fused 1x1 conv for q,k,v -> bf16 hi/lo split, layout [z][h][w]
// ---------------------------------------------------------------------------
__global__ void __launch_bounds__(256) qkv_kernel(
    const float* __restrict__ x,
    const float* __restrict__ Wq, const float* __restrict__ bq,
    const float* __restrict__ Wk, const float* __restrict__ bk,
    const float* __restrict__ Wv, const float* __restrict__ bv)
{
    __shared__ float Xs[64][68];
    __shared__ float WsT[64][68];

    const int t  = threadIdx.x;
    const int b  = blockIdx.y;
    const int p0 = blockIdx.x * 64;
    const int tx = t & 15;
    const int ty = t >> 4;

    {
        const float* xb = x + (size_t)b * CHWn + p0;
        const int row  = t >> 4;
        const int col4 = (t & 15) * 4;
        #pragma unroll
        for (int c0 = 0; c0 < 64; c0 += 16) {
            float4 v4 = *reinterpret_cast<const float4*>(xb + (size_t)(c0 + row) * HWn + col4);
            *reinterpret_cast<float4*>(&Xs[c0 + row][col4]) = v4;
        }
    }

    const float* Wmats[3]  = {Wq, Wk, Wv};
    const float* biases[3] = {bq, bk, bv};
    __nv_bfloat16* outs_hi[3] = {g_qh, g_kh, g_vh};
    __nv_bfloat16* outs_lo[3] = {g_ql, g_kl, g_vl};

    for (int m = 0; m < 3; m++) {
        __syncthreads();
        const float* Wsrc = Wmats[m];
        for (int idx = t; idx < 4096; idx += 256)
            WsT[idx & 63][idx >> 6] = Wsrc[idx];
        __syncthreads();

        float acc[4][4] = {};
        #pragma unroll
        for (int k = 0; k < 64; k++) {
            float4 wv = *reinterpret_cast<const float4*>(&WsT[k][ty * 4]);
            float4 xv = *reinterpret_cast<const float4*>(&Xs[k][tx * 4]);
            float wa[4] = {wv.x, wv.y, wv.z, wv.w};
            float xa[4] = {xv.x, xv.y, xv.z, xv.w};
            #pragma unroll
            for (int oo = 0; oo < 4; oo++)
                #pragma unroll
                for (int pp = 0; pp < 4; pp++)
                    acc[oo][pp] += wa[oo] * xa[pp];
        }

        const float* bsrc = biases[m];
        __nv_bfloat16* dh = outs_hi[m] + (size_t)b * CHWn + p0;
        __nv_bfloat16* dl = outs_lo[m] + (size_t)b * CHWn + p0;
        #pragma unroll
        for (int oo = 0; oo < 4; oo++) {
            const int o = ty * 4 + oo;
            const float bb = bsrc[o];
            __nv_bfloat16 h4[4], l4[4];
            #pragma unroll
            for (int pp = 0; pp < 4; pp++)
                split_bf16(acc[oo][pp] + bb, h4[pp], l4[pp]);
            *reinterpret_cast<uint2*>(dh + (size_t)o * HWn + tx * 4) = *reinterpret_cast<uint2*>(h4);
            *reinterpret_cast<uint2*>(dl + (size_t)o * HWn + tx * 4) = *reinterpret_cast<uint2*>(l4);
        }
    }
}

// ---------------------------------------------------------------------------
// Kernel B1: qtk GEMM. attn[z,i,j] = sum_h q[z,h,i] k[z,h,j].
// A=[k][m] (trans ldmatrix), B=[k][n] (trans ldmatrix). 128x128 CTA tile,
// K-chunks of 16, cp.async double-buffered STATIC smem (34816 B < 48K).
// 3 split terms: AhBh + AhBl + AlBh, fp32 accum.
// ---------------------------------------------------------------------------
__global__ void __launch_bounds__(256) gemm_qtk_kernel()
{
    constexpr int OFF_AL = 4352;      // A tile: [16][136] bf16 = 4352 B
    constexpr int OFF_BH = 8704;
    constexpr int OFF_BL = 13056;
    constexpr int STAGE  = 17408;

    __shared__ __align__(16) char smem[2 * STAGE];
    const uint32_t sb = smem_to_u32(smem);

    const int t    = threadIdx.x;
    const int lane = t & 31;
    const int wid  = t >> 5;
    const int z    = blockIdx.y;
    const int m0   = (blockIdx.x & 1) * 128;
    const int n0   = (blockIdx.x >> 1) * 128;
    const size_t zoff = (size_t)z * HWn;

    const __nv_bfloat16* pAh = g_qh + zoff;
    const __nv_bfloat16* pAl = g_ql + zoff;
    const __nv_bfloat16* pBh = g_kh + zoff;
    const __nv_bfloat16* pBl = g_kl + zoff;

    const int mw = (wid & 3) * 32;
    const int nw = (wid >> 2) * 64;

    float acc[2][8][4] = {};

    auto copy_chunk = [&](int kc, int stg) {
        const uint32_t s0 = sb + (uint32_t)stg * STAGE;
        const int k0  = kc * 16;
        const int row = t >> 4;           // 0..15
        const int c   = t & 15;           // 0..15 (16B chunks over 128 elems)
        const uint32_t so = (uint32_t)(row * 272 + c * 16);
        cp16(s0 + so,          pAh + (size_t)(k0 + row) * Wn + m0 + c * 8);
        cp16(s0 + OFF_AL + so, pAl + (size_t)(k0 + row) * Wn + m0 + c * 8);
        cp16(s0 + OFF_BH + so, pBh + (size_t)(k0 + row) * Wn + n0 + c * 8);
        cp16(s0 + OFF_BL + so, pBl + (size_t)(k0 + row) * Wn + n0 + c * 8);
    };

    auto compute = [&](int stg) {
        const uint32_t s0 = sb + (uint32_t)stg * STAGE;
        uint32_t ah[2][4], al[2][4];
        #pragma unroll
        for (int mt = 0; mt < 2; mt++) {
            int kk = (lane & 7) + ((lane >> 4) << 3);
            int mm = mw + mt * 16 + ((lane >> 3) & 1) * 8;
            uint32_t rel = (uint32_t)(kk * 272 + mm * 2);
            ldsm_x4_t(ah[mt], s0 + rel);
            ldsm_x4_t(al[mt], s0 + OFF_AL + rel);
        }
        #pragma unroll
        for (int np = 0; np < 4; np++) {
            int kk = (lane & 7) + ((lane >> 3) & 1) * 8;
            int nn = nw + np * 16 + ((lane >> 4) & 1) * 8;
            uint32_t rel = (uint32_t)(kk * 272 + nn * 2);
            uint32_t bh[4], bl[4];
            ldsm_x4_t(bh, s0 + OFF_BH + rel);
            ldsm_x4_t(bl, s0 + OFF_BL + rel);
            #pragma unroll
            for (int mt = 0; mt < 2; mt++) {
                #pragma unroll
                for (int h = 0; h < 2; h++) {
                    float* c = acc[mt][np * 2 + h];
                    mma16816(c, ah[mt], bh + 2 * h);
                    mma16816(c, ah[mt], bl + 2 * h);
                    mma16816(c, al[mt], bh + 2 * h);
                }
            }
        }
    };

    copy_chunk(0, 0);
    cp_commit();
    for (int kc = 0; kc < 16; kc++) {
        if (kc < 15) { copy_chunk(kc + 1, (kc + 1) & 1); cp_commit(); cp_wait<1>(); }
        else         { cp_wait<0>(); }
        __syncthreads();
        compute(kc & 1);
        __syncthreads();
    }

    const int g  = lane >> 2;
    const int tg = lane & 3;
    #pragma unroll
    for (int mt = 0; mt < 2; mt++) {
        const int r0 = m0 + mw + mt * 16 + g;
        #pragma unroll
        for (int nj = 0; nj < 8; nj++) {
            const int col = n0 + nw + nj * 8 + tg * 2;
            *reinterpret_cast<float2*>(g_attn + zoff + (size_t)r0 * Wn + col) =
                make_float2(acc[mt][nj][0], acc[mt][nj][1]);
            *reinterpret_cast<float2*>(g_attn + zoff + (size_t)(r0 + 8) * Wn + col) =
                make_float2(acc[mt][nj][2], acc[mt][nj][3]);
        }
    }
}

// ---------------------------------------------------------------------------
// Kernel B2: av GEMM. out[z,i,j] = sum_m attn[z,i,m] v[z,m,j].
// A=[i][m] row-major (non-trans ldmatrix), B=[m][j] (trans ldmatrix).
// Static smem 41984 B < 48K.
// ---------------------------------------------------------------------------
__global__ void __launch_bounds__(256) gemm_av_kernel(float* __restrict__ out)
{
    constexpr int APITCH = 48;        // bytes per A row: 16 k-elems (32B) + pad
    constexpr int OFF_AL = 6144;      // A tile: 128 * 48 B
    constexpr int OFF_BH = 12288;
    constexpr int OFF_BL = 16640;     // B tile: [16][136] bf16 = 4352 B
    constexpr int STAGE  = 20992;

    __shared__ __align__(16) char smem[2 * STAGE];
    const uint32_t sb = smem_to_u32(smem);

    const int t    = threadIdx.x;
    const int lane = t & 31;
    const int wid  = t >> 5;
    const int z    = blockIdx.y;
    const int m0   = (blockIdx.x & 1) * 128;
    const int n0   = (blockIdx.x >> 1) * 128;
    const size_t zoff = (size_t)z * HWn;

    const __nv_bfloat16* pAh = g_ah + zoff;
    const __nv_bfloat16* pAl = g_al + zoff;
    const __nv_bfloat16* pBh = g_vh + zoff;
    const __nv_bfloat16* pBl = g_vl + zoff;

    const int mw = (wid & 3) * 32;
    const int nw = (wid >> 2) * 64;

    float acc[2][8][4] = {};

    auto copy_chunk = [&](int kc, int stg) {
        const uint32_t s0 = sb + (uint32_t)stg * STAGE;
        const int k0 = kc * 16;
        {   // A tile: [128 rows][16 k]
            const int row = t >> 1;       // 0..127
            const int c   = t & 1;        // 0..1 (16B chunks over 32B row)
            const uint32_t so = (uint32_t)(row * APITCH + c * 16);
            cp16(s0 + so,          pAh + (size_t)(m0 + row) * Wn + k0 + c * 8);
            cp16(s0 + OFF_AL + so, pAl + (size_t)(m0 + row) * Wn + k0 + c * 8);
        }
        {   // B tile: [16 rows][128 n]
            const int row = t >> 4;
            const int c   = t & 15;
            const uint32_t so = (uint32_t)(row * 272 + c * 16);
            cp16(s0 + OFF_BH + so, pBh + (size_t)(k0 + row) * Wn + n0 + c * 8);
            cp16(s0 + OFF_BL + so, pBl + (size_t)(k0 + row) * Wn + n0 + c * 8);
        }
    };

    auto compute = [&](int stg) {
        const uint32_t s0 = sb + (uint32_t)stg * STAGE;
        uint32_t ah[2][4], al[2][4];
        #pragma unroll
        for (int mt = 0; mt < 2; mt++) {
            int mm = mw + mt * 16 + (lane & 15);
            int kk = ((lane >> 4) & 1) * 8;
            uint32_t rel = (uint32_t)(mm * APITCH + kk * 2);
            ldsm_x4(ah[mt], s0 + rel);
            ldsm_x4(al[mt], s0 + OFF_AL + rel);
        }
        #pragma unroll
        for (int np = 0; np < 4; np++) {
            int kk = (lane & 7) + ((lane >> 3) & 1) * 8;
            int nn = nw + np * 16 + ((lane >> 4) & 1) * 8;
            uint32_t rel = (uint32_t)(kk * 272 + nn * 2);
            uint32_t bh[4], bl[4];
            ldsm_x4_t(bh, s0 + OFF_BH + rel);
            ldsm_x4_t(bl, s0 + OFF_BL + rel);
            #pragma unroll
            for (int mt = 0; mt < 2; mt++) {
                #pragma unroll
                for (int h = 0; h < 2; h++) {
                    float* c = acc[mt][np * 2 + h];
                    mma16816(c, ah[mt], bh + 2 * h);
                    mma16816(c, ah[mt], bl + 2 * h);
                    mma16816(c, al[mt], bh + 2 * h);
                }
            }
        }
    };

    copy_chunk(0, 0);
    cp_commit();
    for (int kc = 0; kc < 16; kc++) {
        if (kc < 15) { copy_chunk(kc + 1, (kc + 1) & 1); cp_commit(); cp_wait<1>(); }
        else         { cp_wait<0>(); }
        __syncthreads();
        compute(kc & 1);
        __syncthreads();
    }

    const int g  = lane >> 2;
    const int tg = lane & 3;
    #pragma unroll
    for (int mt = 0; mt < 2; mt++) {
        const int r0 = m0 + mw + mt * 16 + g;
        #pragma unroll
        for (int nj = 0; nj < 8; nj++) {
            const int col = n0 + nw + nj * 8 + tg * 2;
            *reinterpret_cast<float2*>(out + zoff + (size_t)r0 * Wn + col) =
                make_float2(acc[mt][nj][0], acc[mt][nj][1]);
            *reinterpret_cast<float2*>(out + zoff + (size_t)(r0 + 8) * Wn + col) =
                make_float2(acc[mt][nj][2], acc[mt][nj][3]);
        }
    }
}

// ---------------------------------------------------------------------------
// Kernel C: softmax over channel axis (fp32 in, bf16 hi/lo out)
// ---------------------------------------------------------------------------
__global__ void __launch_bounds__(256) softmax_split_kernel()
{
    const int idx = blockIdx.x * 256 + threadIdx.x;   // 0 .. B*HW-1
    const int b   = idx >> 16;
    const int ij  = idx & 65535;
    const size_t base = (size_t)b * CHWn + ij;

    float v[64];
    float mx = -INFINITY;
    #pragma unroll
    for (int c = 0; c < 64; c++) {
        v[c] = g_attn[base + (size_t)c * HWn];
        mx = fmaxf(mx, v[c]);
    }
    float s = 0.0f;
    #pragma unroll
    for (int c = 0; c < 64; c++) {
        v[c] = expf(v[c] - mx);
        s += v[c];
    }
    const float inv = 1.0f / s;
    #pragma unroll
    for (int c = 0; c < 64; c++) {
        float p = v[c] * inv;
        __nv_bfloat16 hi, lo;
        split_bf16(p, hi, lo);
        g_ah[base + (size_t)c * HWn] = hi;
        g_al[base + (size_t)c * HWn] = lo;
    }
}

// ---------------------------------------------------------------------------
// Launch — no dynamic smem, no attribute calls, plain default-stream launches.
// ---------------------------------------------------------------------------
extern "C" void kernel_launch(void* const* d_in, const int* in_sizes, int n_in,
                              void* d_out, int out_size)
{
    const float* x  = (const float*)d_in[0];
    const float* Wq = (const float*)d_in[1];
    const float* bq = (const float*)d_in[2];
    const float* Wk = (const float*)d_in[3];
    const float* bk = (const float*)d_in[4];
    const float* Wv = (const float*)d_in[5];
    const float* bv = (const float*)d_in[6];
    float* out = (float*)d_out;

    // 1) q,k,v = 1x1 conv(x), written as bf16 hi/lo in [z][h][w]
    qkv_kernel<<<dim3(HWn / 64, Bn), 256>>>(x, Wq, bq, Wk, bk, Wv, bv);

    // 2) attn logits: attn[z,i,j] = sum_h q[z,h,i] k[z,h,j]
    gemm_qtk_kernel<<<dim3(4, NZ), 256>>>();

    // 3) softmax over channels, emit bf16 hi/lo ([i][m] row-major for next GEMM)
    softmax_split_kernel<<<(Bn * HWn) / 256, 256>>>();

    // 4) out[z,i,j] = sum_m attn[z,i,m] v[z,m,j]
    gemm_av_kernel<<<dim3(4, NZ), 256>>>(out);
}

// round 9
// speedup vs baseline: 2.1131x; 1.4388x over previous
#include <cuda_runtime.h>
#include <cuda_bf16.h>
#include <math.h>
#include <stdint.h>

// ---------------------------------------------------------------------------
// Problem constants
// ---------------------------------------------------------------------------
static constexpr int Bn = 8, Cn = 64, Hn = 256, Wn = 256;
static constexpr int HWn  = Hn * Wn;       // 65536
static constexpr int CHWn = Cn * HWn;      // 4194304
static constexpr int NZ   = Bn * Cn;       // 512
static constexpr int NTOT = 33554432;      // B*C*H*W

// ---------------------------------------------------------------------------
// Scratch (device globals: allocation-free contract)
// ---------------------------------------------------------------------------
__device__ __nv_bfloat16 g_qh[NTOT], g_ql[NTOT];
__device__ __nv_bfloat16 g_kh[NTOT], g_kl[NTOT];
__device__ __nv_bfloat16 g_vh[NTOT], g_vl[NTOT];
__device__ float         g_attn[NTOT];                 // fp32 logits [z][i][j]
__device__ __nv_bfloat16 g_ah[NTOT], g_al[NTOT];       // softmaxed attn split
__device__ __nv_bfloat16 g_Wh[3 * 4096], g_Wl[3 * 4096];  // pre-split weights

// ---------------------------------------------------------------------------
// PTX helpers — sm_80-era features only (compile clean at .target sm_103)
// ---------------------------------------------------------------------------
__device__ __forceinline__ uint32_t smem_to_u32(const void* p) {
    uint32_t a;
    asm("{ .reg .u64 t; cvta.to.shared.u64 t, %1; cvt.u32.u64 %0, t; }"
        : "=r"(a) : "l"(p));
    return a;
}

__device__ __forceinline__ void cp16(uint32_t s, const void* g) {
    asm volatile("cp.async.cg.shared.global [%0], [%1], 16;"
                 :: "r"(s), "l"(g) : "memory");
}
__device__ __forceinline__ void cp_commit() {
    asm volatile("cp.async.commit_group;" ::: "memory");
}
template <int N>
__device__ __forceinline__ void cp_wait() {
    asm volatile("cp.async.wait_group %0;" :: "n"(N) : "memory");
}

__device__ __forceinline__ void ldsm_x4(uint32_t* r, uint32_t addr) {
    asm volatile("ldmatrix.sync.aligned.m8n8.x4.shared.b16 {%0,%1,%2,%3}, [%4];"
                 : "=r"(r[0]), "=r"(r[1]), "=r"(r[2]), "=r"(r[3]) : "r"(addr));
}
__device__ __forceinline__ void ldsm_x4_t(uint32_t* r, uint32_t addr) {
    asm volatile("ldmatrix.sync.aligned.m8n8.x4.trans.shared.b16 {%0,%1,%2,%3}, [%4];"
                 : "=r"(r[0]), "=r"(r[1]), "=r"(r[2]), "=r"(r[3]) : "r"(addr));
}

__device__ __forceinline__ void mma16816(float* c, const uint32_t* a, const uint32_t* b) {
    asm volatile(
        "mma.sync.aligned.m16n8k16.row.col.f32.bf16.bf16.f32 "
        "{%0,%1,%2,%3}, {%4,%5,%6,%7}, {%8,%9}, {%0,%1,%2,%3};"
        : "+f"(c[0]), "+f"(c[1]), "+f"(c[2]), "+f"(c[3])
        : "r"(a[0]), "r"(a[1]), "r"(a[2]), "r"(a[3]), "r"(b[0]), "r"(b[1]));
}

__device__ __forceinline__ void split_bf16(float x, __nv_bfloat16& hi, __nv_bfloat16& lo) {
    hi = __float2bfloat16(x);
    lo = __float2bfloat16(x - __bfloat162float(hi));
}

// ---------------------------------------------------------------------------
// Kernel W: one-time split of Wq/Wk/Wv into bf16 hi/lo (3 x 64 x 64)
// ---------------------------------------------------------------------------
__global__ void __launch_bounds__(256) wsplit_kernel(
    const float* __restrict__ Wq, const float* __restrict__ Wk,
    const float* __restrict__ Wv)
{
    const int t = blockIdx.x * 256 + threadIdx.x;
    if (t >= 3 * 4096) return;
    const int m = t >> 12, i = t & 4095;
    const float* src = (m == 0) ? Wq : (m == 1) ? Wk : Wv;
    __nv_bfloat16 hi, lo;
    split_bf16(src[i], hi, lo);
    g_Wh[t] = hi;
    g_Wl[t] = lo;
}

// ---------------------------------------------------------------------------
// Kernel A: tensor-core 1x1 conv. Per CTA: batch b, 64 pixels, all 3 matrices.
// GEMM view: M=o(64) x N=p(64) x K=c(64).
//   A = W[o][c] row-major  -> non-trans ldmatrix (proven av-A mapping)
//   B = x[c][p] K-major    -> trans ldmatrix (proven qtk-B mapping)
// x converted fp32 -> bf16 hi/lo in-register, staged once, reused 3x.
// 3 split terms: WhXh + WhXl + WlXh, fp32 accum, bias in epilogue.
// ---------------------------------------------------------------------------
__global__ void __launch_bounds__(256) qkv_mma_kernel(
    const float* __restrict__ x,
    const float* __restrict__ bq, const float* __restrict__ bk,
    const float* __restrict__ bv)
{
    constexpr int XP = 72;   // pitch in elems (144 B)
    constexpr int WP = 72;

    __shared__ __align__(16) __nv_bfloat16 Xh[64 * XP], Xl[64 * XP];
    __shared__ __align__(16) __nv_bfloat16 Wh[64 * WP], Wl[64 * WP];

    const uint32_t sXh = smem_to_u32(Xh), sXl = smem_to_u32(Xl);
    const uint32_t sWh = smem_to_u32(Wh), sWl = smem_to_u32(Wl);

    const int t    = threadIdx.x;
    const int lane = t & 31;
    const int wid  = t >> 5;
    const int b    = blockIdx.y;
    const int p0   = blockIdx.x * 64;

    // --- stage x tile [c=64][p=64], split to hi/lo ---
    {
        const int c  = t >> 2;          // 0..63
        const int pg = (t & 3) * 16;    // 0,16,32,48
        const float* xrow = x + ((size_t)(b * Cn + c)) * HWn + p0 + pg;
        __nv_bfloat16 hb[16], lb[16];
        #pragma unroll
        for (int j = 0; j < 16; j += 4) {
            float4 v4 = *reinterpret_cast<const float4*>(xrow + j);
            split_bf16(v4.x, hb[j + 0], lb[j + 0]);
            split_bf16(v4.y, hb[j + 1], lb[j + 1]);
            split_bf16(v4.z, hb[j + 2], lb[j + 2]);
            split_bf16(v4.w, hb[j + 3], lb[j + 3]);
        }
        *reinterpret_cast<uint4*>(&Xh[c * XP + pg])     = reinterpret_cast<uint4*>(hb)[0];
        *reinterpret_cast<uint4*>(&Xh[c * XP + pg + 8]) = reinterpret_cast<uint4*>(hb)[1];
        *reinterpret_cast<uint4*>(&Xl[c * XP + pg])     = reinterpret_cast<uint4*>(lb)[0];
        *reinterpret_cast<uint4*>(&Xl[c * XP + pg + 8]) = reinterpret_cast<uint4*>(lb)[1];
    }

    const float* biases[3] = {bq, bk, bv};
    __nv_bfloat16* outs_hi[3] = {g_qh, g_kh, g_vh};
    __nv_bfloat16* outs_lo[3] = {g_ql, g_kl, g_vl};

    const int mw = (wid & 3) * 16;   // o-offset of warp
    const int nw = (wid >> 2) * 32;  // p-offset of warp
    const int g  = lane >> 2;
    const int tg = lane & 3;

    for (int m = 0; m < 3; m++) {
        __syncthreads();   // prior compute done before W overwrite
        {   // stage W[o][c] hi/lo (row-major, k contiguous)
            const int o  = t >> 2;
            const int cg = (t & 3) * 16;
            const __nv_bfloat16* wh = g_Wh + m * 4096 + o * 64 + cg;
            const __nv_bfloat16* wl = g_Wl + m * 4096 + o * 64 + cg;
            *reinterpret_cast<uint4*>(&Wh[o * WP + cg])     = reinterpret_cast<const uint4*>(wh)[0];
            *reinterpret_cast<uint4*>(&Wh[o * WP + cg + 8]) = reinterpret_cast<const uint4*>(wh)[1];
            *reinterpret_cast<uint4*>(&Wl[o * WP + cg])     = reinterpret_cast<const uint4*>(wl)[0];
            *reinterpret_cast<uint4*>(&Wl[o * WP + cg + 8]) = reinterpret_cast<const uint4*>(wl)[1];
        }
        __syncthreads();   // W + X visible (covers X stores on m==0)

        float acc[4][4] = {};
        #pragma unroll
        for (int ks = 0; ks < 4; ks++) {
            uint32_t ah[4], al[4];
            {   // A = W rows (o), non-trans (av-A mapping)
                int mm = mw + (lane & 15);
                int kk = ks * 16 + ((lane >> 4) & 1) * 8;
                uint32_t rel = (uint32_t)((mm * WP + kk) * 2);
                ldsm_x4(ah, sWh + rel);
                ldsm_x4(al, sWl + rel);
            }
            #pragma unroll
            for (int np = 0; np < 2; np++) {
                int kk = ks * 16 + (lane & 7) + ((lane >> 3) & 1) * 8;
                int nn = nw + np * 16 + ((lane >> 4) & 1) * 8;
                uint32_t rel = (uint32_t)((kk * XP + nn) * 2);
                uint32_t bh[4], bl[4];
                ldsm_x4_t(bh, sXh + rel);
                ldsm_x4_t(bl, sXl + rel);
                #pragma unroll
                for (int h = 0; h < 2; h++) {
                    float* c = acc[np * 2 + h];
                    mma16816(c, ah, bh + 2 * h);
                    mma16816(c, ah, bl + 2 * h);
                    mma16816(c, al, bh + 2 * h);
                }
            }
        }

        // epilogue: bias add, split, store bf16x2 pairs (consecutive pixels)
        const float* bias = biases[m];
        const float bo0 = bias[mw + g];
        const float bo1 = bias[mw + 8 + g];
        __nv_bfloat16* dh = outs_hi[m];
        __nv_bfloat16* dl = outs_lo[m];
        const size_t row0 = (size_t)(b * Cn + mw + g) * HWn + p0;
        const size_t row1 = (size_t)(b * Cn + mw + 8 + g) * HWn + p0;
        #pragma unroll
        for (int nj = 0; nj < 4; nj++) {
            const int p = nw + nj * 8 + tg * 2;
            __nv_bfloat16 h0, l0, h1, l1;
            // row o = mw+g
            split_bf16(acc[nj][0] + bo0, h0, l0);
            split_bf16(acc[nj][1] + bo0, h1, l1);
            __nv_bfloat162 hp, lp;
            hp.x = h0; hp.y = h1; lp.x = l0; lp.y = l1;
            *reinterpret_cast<__nv_bfloat162*>(dh + row0 + p) = hp;
            *reinterpret_cast<__nv_bfloat162*>(dl + row0 + p) = lp;
            // row o = mw+8+g
            split_bf16(acc[nj][2] + bo1, h0, l0);
            split_bf16(acc[nj][3] + bo1, h1, l1);
            hp.x = h0; hp.y = h1; lp.x = l0; lp.y = l1;
            *reinterpret_cast<__nv_bfloat162*>(dh + row1 + p) = hp;
            *reinterpret_cast<__nv_bfloat162*>(dl + row1 + p) = lp;
        }
    }
}

// ---------------------------------------------------------------------------
// Kernel B1: qtk GEMM. attn[z,i,j] = sum_h q[z,h,i] k[z,h,j].
// 128x128 CTA tile, K-chunks of 16, cp.async double-buffered static smem.
// __launch_bounds__(256, 2): cap regs at 128 -> 2 CTAs/SM.
// ---------------------------------------------------------------------------
__global__ void __launch_bounds__(256, 2) gemm_qtk_kernel()
{
    constexpr int OFF_AL = 4352;      // A tile: [16][136] bf16 = 4352 B
    constexpr int OFF_BH = 8704;
    constexpr int OFF_BL = 13056;
    constexpr int STAGE  = 17408;

    __shared__ __align__(16) char smem[2 * STAGE];
    const uint32_t sb = smem_to_u32(smem);

    const int t    = threadIdx.x;
    const int lane = t & 31;
    const int wid  = t >> 5;
    const int z    = blockIdx.y;
    const int m0   = (blockIdx.x & 1) * 128;
    const int n0   = (blockIdx.x >> 1) * 128;
    const size_t zoff = (size_t)z * HWn;

    const __nv_bfloat16* pAh = g_qh + zoff;
    const __nv_bfloat16* pAl = g_ql + zoff;
    const __nv_bfloat16* pBh = g_kh + zoff;
    const __nv_bfloat16* pBl = g_kl + zoff;

    const int mw = (wid & 3) * 32;
    const int nw = (wid >> 2) * 64;

    float acc[2][8][4] = {};

    auto copy_chunk = [&](int kc, int stg) {
        const uint32_t s0 = sb + (uint32_t)stg * STAGE;
        const int k0  = kc * 16;
        const int row = t >> 4;
        const int c   = t & 15;
        const uint32_t so = (uint32_t)(row * 272 + c * 16);
        cp16(s0 + so,          pAh + (size_t)(k0 + row) * Wn + m0 + c * 8);
        cp16(s0 + OFF_AL + so, pAl + (size_t)(k0 + row) * Wn + m0 + c * 8);
        cp16(s0 + OFF_BH + so, pBh + (size_t)(k0 + row) * Wn + n0 + c * 8);
        cp16(s0 + OFF_BL + so, pBl + (size_t)(k0 + row) * Wn + n0 + c * 8);
    };

    auto compute = [&](int stg) {
        const uint32_t s0 = sb + (uint32_t)stg * STAGE;
        uint32_t ah[2][4], al[2][4];
        #pragma unroll
        for (int mt = 0; mt < 2; mt++) {
            int kk = (lane & 7) + ((lane >> 4) << 3);
            int mm = mw + mt * 16 + ((lane >> 3) & 1) * 8;
            uint32_t rel = (uint32_t)(kk * 272 + mm * 2);
            ldsm_x4_t(ah[mt], s0 + rel);
            ldsm_x4_t(al[mt], s0 + OFF_AL + rel);
        }
        #pragma unroll
        for (int np = 0; np < 4; np++) {
            int kk = (lane & 7) + ((lane >> 3) & 1) * 8;
            int nn = nw + np * 16 + ((lane >> 4) & 1) * 8;
            uint32_t rel = (uint32_t)(kk * 272 + nn * 2);
            uint32_t bh[4], bl[4];
            ldsm_x4_t(bh, s0 + OFF_BH + rel);
            ldsm_x4_t(bl, s0 + OFF_BL + rel);
            #pragma unroll
            for (int mt = 0; mt < 2; mt++) {
                #pragma unroll
                for (int h = 0; h < 2; h++) {
                    float* c = acc[mt][np * 2 + h];
                    mma16816(c, ah[mt], bh + 2 * h);
                    mma16816(c, ah[mt], bl + 2 * h);
                    mma16816(c, al[mt], bh + 2 * h);
                }
            }
        }
    };

    copy_chunk(0, 0);
    cp_commit();
    for (int kc = 0; kc < 16; kc++) {
        if (kc < 15) { copy_chunk(kc + 1, (kc + 1) & 1); cp_commit(); cp_wait<1>(); }
        else         { cp_wait<0>(); }
        __syncthreads();
        compute(kc & 1);
        __syncthreads();
    }

    const int g  = lane >> 2;
    const int tg = lane & 3;
    #pragma unroll
    for (int mt = 0; mt < 2; mt++) {
        const int r0 = m0 + mw + mt * 16 + g;
        #pragma unroll
        for (int nj = 0; nj < 8; nj++) {
            const int col = n0 + nw + nj * 8 + tg * 2;
            *reinterpret_cast<float2*>(g_attn + zoff + (size_t)r0 * Wn + col) =
                make_float2(acc[mt][nj][0], acc[mt][nj][1]);
            *reinterpret_cast<float2*>(g_attn + zoff + (size_t)(r0 + 8) * Wn + col) =
                make_float2(acc[mt][nj][2], acc[mt][nj][3]);
        }
    }
}

// ---------------------------------------------------------------------------
// Kernel B2: av GEMM. out[z,i,j] = sum_m attn[z,i,m] v[z,m,j].
// ---------------------------------------------------------------------------
__global__ void __launch_bounds__(256, 2) gemm_av_kernel(float* __restrict__ out)
{
    constexpr int APITCH = 48;
    constexpr int OFF_AL = 6144;
    constexpr int OFF_BH = 12288;
    constexpr int OFF_BL = 16640;
    constexpr int STAGE  = 20992;

    __shared__ __align__(16) char smem[2 * STAGE];
    const uint32_t sb = smem_to_u32(smem);

    const int t    = threadIdx.x;
    const int lane = t & 31;
    const int wid  = t >> 5;
    const int z    = blockIdx.y;
    const int m0   = (blockIdx.x & 1) * 128;
    const int n0   = (blockIdx.x >> 1) * 128;
    const size_t zoff = (size_t)z * HWn;

    const __nv_bfloat16* pAh = g_ah + zoff;
    const __nv_bfloat16* pAl = g_al + zoff;
    const __nv_bfloat16* pBh = g_vh + zoff;
    const __nv_bfloat16* pBl = g_vl + zoff;

    const int mw = (wid & 3) * 32;
    const int nw = (wid >> 2) * 64;

    float acc[2][8][4] = {};

    auto copy_chunk = [&](int kc, int stg) {
        const uint32_t s0 = sb + (uint32_t)stg * STAGE;
        const int k0 = kc * 16;
        {
            const int row = t >> 1;
            const int c   = t & 1;
            const uint32_t so = (uint32_t)(row * APITCH + c * 16);
            cp16(s0 + so,          pAh + (size_t)(m0 + row) * Wn + k0 + c * 8);
            cp16(s0 + OFF_AL + so, pAl + (size_t)(m0 + row) * Wn + k0 + c * 8);
        }
        {
            const int row = t >> 4;
            const int c   = t & 15;
            const uint32_t so = (uint32_t)(row * 272 + c * 16);
            cp16(s0 + OFF_BH + so, pBh + (size_t)(k0 + row) * Wn + n0 + c * 8);
            cp16(s0 + OFF_BL + so, pBl + (size_t)(k0 + row) * Wn + n0 + c * 8);
        }
    };

    auto compute = [&](int stg) {
        const uint32_t s0 = sb + (uint32_t)stg * STAGE;
        uint32_t ah[2][4], al[2][4];
        #pragma unroll
        for (int mt = 0; mt < 2; mt++) {
            int mm = mw + mt * 16 + (lane & 15);
            int kk = ((lane >> 4) & 1) * 8;
            uint32_t rel = (uint32_t)(mm * APITCH + kk * 2);
            ldsm_x4(ah[mt], s0 + rel);
            ldsm_x4(al[mt], s0 + OFF_AL + rel);
        }
        #pragma unroll
        for (int np = 0; np < 4; np++) {
            int kk = (lane & 7) + ((lane >> 3) & 1) * 8;
            int nn = nw + np * 16 + ((lane >> 4) & 1) * 8;
            uint32_t rel = (uint32_t)(kk * 272 + nn * 2);
            uint32_t bh[4], bl[4];
            ldsm_x4_t(bh, s0 + OFF_BH + rel);
            ldsm_x4_t(bl, s0 + OFF_BL + rel);
            #pragma unroll
            for (int mt = 0; mt < 2; mt++) {
                #pragma unroll
                for (int h = 0; h < 2; h++) {
                    float* c = acc[mt][np * 2 + h];
                    mma16816(c, ah[mt], bh + 2 * h);
                    mma16816(c, ah[mt], bl + 2 * h);
                    mma16816(c, al[mt], bh + 2 * h);
                }
            }
        }
    };

    copy_chunk(0, 0);
    cp_commit();
    for (int kc = 0; kc < 16; kc++) {
        if (kc < 15) { copy_chunk(kc + 1, (kc + 1) & 1); cp_commit(); cp_wait<1>(); }
        else         { cp_wait<0>(); }
        __syncthreads();
        compute(kc & 1);
        __syncthreads();
    }

    const int g  = lane >> 2;
    const int tg = lane & 3;
    #pragma unroll
    for (int mt = 0; mt < 2; mt++) {
        const int r0 = m0 + mw + mt * 16 + g;
        #pragma unroll
        for (int nj = 0; nj < 8; nj++) {
            const int col = n0 + nw + nj * 8 + tg * 2;
            *reinterpret_cast<float2*>(out + zoff + (size_t)r0 * Wn + col) =
                make_float2(acc[mt][nj][0], acc[mt][nj][1]);
            *reinterpret_cast<float2*>(out + zoff + (size_t)(r0 + 8) * Wn + col) =
                make_float2(acc[mt][nj][2], acc[mt][nj][3]);
        }
    }
}

// ---------------------------------------------------------------------------
// Kernel C: softmax over channel axis (fp32 in, bf16 hi/lo out)
// ---------------------------------------------------------------------------
__global__ void __launch_bounds__(256) softmax_split_kernel()
{
    const int idx = blockIdx.x * 256 + threadIdx.x;   // 0 .. B*HW-1
    const int b   = idx >> 16;
    const int ij  = idx & 65535;
    const size_t base = (size_t)b * CHWn + ij;

    float v[64];
    float mx = -INFINITY;
    #pragma unroll
    for (int c = 0; c < 64; c++) {
        v[c] = g_attn[base + (size_t)c * HWn];
        mx = fmaxf(mx, v[c]);
    }
    float s = 0.0f;
    #pragma unroll
    for (int c = 0; c < 64; c++) {
        v[c] = expf(v[c] - mx);
        s += v[c];
    }
    const float inv = 1.0f / s;
    #pragma unroll
    for (int c = 0; c < 64; c++) {
        float p = v[c] * inv;
        __nv_bfloat16 hi, lo;
        split_bf16(p, hi, lo);
        g_ah[base + (size_t)c * HWn] = hi;
        g_al[base + (size_t)c * HWn] = lo;
    }
}

// ---------------------------------------------------------------------------
// Launch — no dynamic smem, no attribute calls, plain default-stream launches.
// ---------------------------------------------------------------------------
extern "C" void kernel_launch(void* const* d_in, const int* in_sizes, int n_in,
                              void* d_out, int out_size)
{
    const float* x  = (const float*)d_in[0];
    const float* Wq = (const float*)d_in[1];
    const float* bq = (const float*)d_in[2];
    const float* Wk = (const float*)d_in[3];
    const float* bk = (const float*)d_in[4];
    const float* Wv = (const float*)d_in[5];
    const float* bv = (const float*)d_in[6];
    float* out = (float*)d_out;

    // 0) split weights to bf16 hi/lo (tiny)
    wsplit_kernel<<<48, 256>>>(Wq, Wk, Wv);

    // 1) q,k,v = 1x1 conv(x) on tensor cores, bf16 hi/lo out in [z][h][w]
    qkv_mma_kernel<<<dim3(HWn / 64, Bn), 256>>>(x, bq, bk, bv);

    // 2) attn logits: attn[z,i,j] = sum_h q[z,h,i] k[z,h,j]
    gemm_qtk_kernel<<<dim3(4, NZ), 256>>>();

    // 3) softmax over channels, emit bf16 hi/lo ([i][m] row-major for next GEMM)
    softmax_split_kernel<<<(Bn * HWn) / 256, 256>>>();

    // 4) out[z,i,j] = sum_m attn[z,i,m] v[z,m,j]
    gemm_av_kernel<<<dim3(4, NZ), 256>>>(out);
}

// round 11
// speedup vs baseline: 2.1152x; 1.0010x over previous
#include <cuda_runtime.h>
#include <cuda_bf16.h>
#include <math.h>
#include <stdint.h>

// ---------------------------------------------------------------------------
// Problem constants
// ---------------------------------------------------------------------------
static constexpr int Bn = 8, Cn = 64, Hn = 256, Wn = 256;
static constexpr int HWn  = Hn * Wn;       // 65536
static constexpr int CHWn = Cn * HWn;      // 4194304
static constexpr int NZ   = Bn * Cn;       // 512
static constexpr int NTOT = 33554432;      // B*C*H*W

// ---------------------------------------------------------------------------
// Scratch (device globals: allocation-free contract)
// ---------------------------------------------------------------------------
__device__ __nv_bfloat16 g_qh[NTOT], g_ql[NTOT];
__device__ __nv_bfloat16 g_kh[NTOT], g_kl[NTOT];
__device__ __nv_bfloat16 g_vh[NTOT], g_vl[NTOT];
__device__ float         g_attn[NTOT];                 // fp32 logits [z][i][j]
__device__ __nv_bfloat16 g_ah[NTOT], g_al[NTOT];       // softmaxed attn split
__device__ __nv_bfloat16 g_Wh[3 * 4096], g_Wl[3 * 4096];  // pre-split weights

// ---------------------------------------------------------------------------
// PTX helpers — sm_80-era features only (compile clean at .target sm_103)
// ---------------------------------------------------------------------------
__device__ __forceinline__ uint32_t smem_to_u32(const void* p) {
    uint32_t a;
    asm("{ .reg .u64 t; cvta.to.shared.u64 t, %1; cvt.u32.u64 %0, t; }"
        : "=r"(a) : "l"(p));
    return a;
}

__device__ __forceinline__ void cp16(uint32_t s, const void* g) {
    asm volatile("cp.async.cg.shared.global [%0], [%1], 16;"
                 :: "r"(s), "l"(g) : "memory");
}
__device__ __forceinline__ void cp_commit() {
    asm volatile("cp.async.commit_group;" ::: "memory");
}
template <int N>
__device__ __forceinline__ void cp_wait() {
    asm volatile("cp.async.wait_group %0;" :: "n"(N) : "memory");
}

__device__ __forceinline__ void ldsm_x4(uint32_t* r, uint32_t addr) {
    asm volatile("ldmatrix.sync.aligned.m8n8.x4.shared.b16 {%0,%1,%2,%3}, [%4];"
                 : "=r"(r[0]), "=r"(r[1]), "=r"(r[2]), "=r"(r[3]) : "r"(addr));
}
__device__ __forceinline__ void ldsm_x4_t(uint32_t* r, uint32_t addr) {
    asm volatile("ldmatrix.sync.aligned.m8n8.x4.trans.shared.b16 {%0,%1,%2,%3}, [%4];"
                 : "=r"(r[0]), "=r"(r[1]), "=r"(r[2]), "=r"(r[3]) : "r"(addr));
}

__device__ __forceinline__ void mma16816(float* c, const uint32_t* a, const uint32_t* b) {
    asm volatile(
        "mma.sync.aligned.m16n8k16.row.col.f32.bf16.bf16.f32 "
        "{%0,%1,%2,%3}, {%4,%5,%6,%7}, {%8,%9}, {%0,%1,%2,%3};"
        : "+f"(c[0]), "+f"(c[1]), "+f"(c[2]), "+f"(c[3])
        : "r"(a[0]), "r"(a[1]), "r"(a[2]), "r"(a[3]), "r"(b[0]), "r"(b[1]));
}

__device__ __forceinline__ void split_bf16(float x, __nv_bfloat16& hi, __nv_bfloat16& lo) {
    hi = __float2bfloat16(x);
    lo = __float2bfloat16(x - __bfloat162float(hi));
}

// ---------------------------------------------------------------------------
// Kernel W: one-time split of Wq/Wk/Wv into bf16 hi/lo (3 x 64 x 64)
// ---------------------------------------------------------------------------
__global__ void __launch_bounds__(256) wsplit_kernel(
    const float* __restrict__ Wq, const float* __restrict__ Wk,
    const float* __restrict__ Wv)
{
    const int t = blockIdx.x * 256 + threadIdx.x;
    if (t >= 3 * 4096) return;
    const int m = t >> 12, i = t & 4095;
    const float* src = (m == 0) ? Wq : (m == 1) ? Wk : Wv;
    __nv_bfloat16 hi, lo;
    split_bf16(src[i], hi, lo);
    g_Wh[t] = hi;
    g_Wl[t] = lo;
}

// ---------------------------------------------------------------------------
// Kernel A: tensor-core 1x1 conv (round-9 proven version).
// Per CTA: batch b, 64 pixels, all 3 matrices. M=o(64) x N=p(64) x K=c(64).
//   A = W[o][c] row-major, pitch 72 -> non-trans ldmatrix
//   B = x[c][p] K-major,  pitch 72 -> trans ldmatrix
// ---------------------------------------------------------------------------
__global__ void __launch_bounds__(256) qkv_mma_kernel(
    const float* __restrict__ x,
    const float* __restrict__ bq, const float* __restrict__ bk,
    const float* __restrict__ bv)
{
    constexpr int XP = 72;   // pitch in elems (144 B)
    constexpr int WP = 72;

    __shared__ __align__(16) __nv_bfloat16 Xh[64 * XP], Xl[64 * XP];
    __shared__ __align__(16) __nv_bfloat16 Wh[64 * WP], Wl[64 * WP];

    const uint32_t sXh = smem_to_u32(Xh), sXl = smem_to_u32(Xl);
    const uint32_t sWh = smem_to_u32(Wh), sWl = smem_to_u32(Wl);

    const int t    = threadIdx.x;
    const int lane = t & 31;
    const int wid  = t >> 5;
    const int b    = blockIdx.y;
    const int p0   = blockIdx.x * 64;

    // --- stage x tile [c=64][p=64], split to hi/lo ---
    {
        const int c  = t >> 2;          // 0..63
        const int pg = (t & 3) * 16;    // 0,16,32,48
        const float* xrow = x + ((size_t)(b * Cn + c)) * HWn + p0 + pg;
        __nv_bfloat16 hb[16], lb[16];
        #pragma unroll
        for (int j = 0; j < 16; j += 4) {
            float4 v4 = *reinterpret_cast<const float4*>(xrow + j);
            split_bf16(v4.x, hb[j + 0], lb[j + 0]);
            split_bf16(v4.y, hb[j + 1], lb[j + 1]);
            split_bf16(v4.z, hb[j + 2], lb[j + 2]);
            split_bf16(v4.w, hb[j + 3], lb[j + 3]);
        }
        *reinterpret_cast<uint4*>(&Xh[c * XP + pg])     = reinterpret_cast<uint4*>(hb)[0];
        *reinterpret_cast<uint4*>(&Xh[c * XP + pg + 8]) = reinterpret_cast<uint4*>(hb)[1];
        *reinterpret_cast<uint4*>(&Xl[c * XP + pg])     = reinterpret_cast<uint4*>(lb)[0];
        *reinterpret_cast<uint4*>(&Xl[c * XP + pg + 8]) = reinterpret_cast<uint4*>(lb)[1];
    }

    const float* biases[3] = {bq, bk, bv};
    __nv_bfloat16* outs_hi[3] = {g_qh, g_kh, g_vh};
    __nv_bfloat16* outs_lo[3] = {g_ql, g_kl, g_vl};

    const int mw = (wid & 3) * 16;   // o-offset of warp
    const int nw = (wid >> 2) * 32;  // p-offset of warp
    const int g  = lane >> 2;
    const int tg = lane & 3;

    for (int m = 0; m < 3; m++) {
        __syncthreads();   // prior compute done before W overwrite
        {   // stage W[o][c] hi/lo (row-major, k contiguous)
            const int o  = t >> 2;
            const int cg = (t & 3) * 16;
            const __nv_bfloat16* wh = g_Wh + m * 4096 + o * 64 + cg;
            const __nv_bfloat16* wl = g_Wl + m * 4096 + o * 64 + cg;
            *reinterpret_cast<uint4*>(&Wh[o * WP + cg])     = reinterpret_cast<const uint4*>(wh)[0];
            *reinterpret_cast<uint4*>(&Wh[o * WP + cg + 8]) = reinterpret_cast<const uint4*>(wh)[1];
            *reinterpret_cast<uint4*>(&Wl[o * WP + cg])     = reinterpret_cast<const uint4*>(wl)[0];
            *reinterpret_cast<uint4*>(&Wl[o * WP + cg + 8]) = reinterpret_cast<const uint4*>(wl)[1];
        }
        __syncthreads();   // W + X visible (covers X stores on m==0)

        float acc[4][4] = {};
        #pragma unroll
        for (int ks = 0; ks < 4; ks++) {
            uint32_t ah[4], al[4];
            {   // A = W rows (o), non-trans
                int mm = mw + (lane & 15);
                int kk = ks * 16 + ((lane >> 4) & 1) * 8;
                uint32_t rel = (uint32_t)((mm * WP + kk) * 2);
                ldsm_x4(ah, sWh + rel);
                ldsm_x4(al, sWl + rel);
            }
            #pragma unroll
            for (int np = 0; np < 2; np++) {
                int kk = ks * 16 + (lane & 7) + ((lane >> 3) & 1) * 8;
                int nn = nw + np * 16 + ((lane >> 4) & 1) * 8;
                uint32_t rel = (uint32_t)((kk * XP + nn) * 2);
                uint32_t bh[4], bl[4];
                ldsm_x4_t(bh, sXh + rel);
                ldsm_x4_t(bl, sXl + rel);
                #pragma unroll
                for (int h = 0; h < 2; h++) {
                    float* c = acc[np * 2 + h];
                    mma16816(c, ah, bh + 2 * h);
                    mma16816(c, ah, bl + 2 * h);
                    mma16816(c, al, bh + 2 * h);
                }
            }
        }

        // epilogue: bias add, split, store bf16x2 pairs (consecutive pixels)
        const float* bias = biases[m];
        const float bo0 = bias[mw + g];
        const float bo1 = bias[mw + 8 + g];
        __nv_bfloat16* dh = outs_hi[m];
        __nv_bfloat16* dl = outs_lo[m];
        const size_t row0 = (size_t)(b * Cn + mw + g) * HWn + p0;
        const size_t row1 = (size_t)(b * Cn + mw + 8 + g) * HWn + p0;
        #pragma unroll
        for (int nj = 0; nj < 4; nj++) {
            const int p = nw + nj * 8 + tg * 2;
            __nv_bfloat16 h0, l0, h1, l1;
            split_bf16(acc[nj][0] + bo0, h0, l0);
            split_bf16(acc[nj][1] + bo0, h1, l1);
            __nv_bfloat162 hp, lp;
            hp.x = h0; hp.y = h1; lp.x = l0; lp.y = l1;
            *reinterpret_cast<__nv_bfloat162*>(dh + row0 + p) = hp;
            *reinterpret_cast<__nv_bfloat162*>(dl + row0 + p) = lp;
            split_bf16(acc[nj][2] + bo1, h0, l0);
            split_bf16(acc[nj][3] + bo1, h1, l1);
            hp.x = h0; hp.y = h1; lp.x = l0; lp.y = l1;
            *reinterpret_cast<__nv_bfloat162*>(dh + row1 + p) = hp;
            *reinterpret_cast<__nv_bfloat162*>(dl + row1 + p) = lp;
        }
    }
}

// ---------------------------------------------------------------------------
// Kernel B1: qtk GEMM. attn[z,i,j] = sum_h q[z,h,i] k[z,h,j].
// 128x128 CTA tile, K-chunks of 16, cp.async double-buffered static smem.
// Single-sync pipeline: wait -> sync -> copy(next) -> compute(cur).
// ---------------------------------------------------------------------------
__global__ void __launch_bounds__(256, 2) gemm_qtk_kernel()
{
    constexpr int OFF_AL = 4352;      // A tile: [16][136] bf16 = 4352 B
    constexpr int OFF_BH = 8704;
    constexpr int OFF_BL = 13056;
    constexpr int STAGE  = 17408;

    __shared__ __align__(16) char smem[2 * STAGE];
    const uint32_t sb = smem_to_u32(smem);

    const int t    = threadIdx.x;
    const int lane = t & 31;
    const int wid  = t >> 5;
    const int z    = blockIdx.y;
    const int m0   = (blockIdx.x & 1) * 128;
    const int n0   = (blockIdx.x >> 1) * 128;
    const size_t zoff = (size_t)z * HWn;

    const __nv_bfloat16* pAh = g_qh + zoff;
    const __nv_bfloat16* pAl = g_ql + zoff;
    const __nv_bfloat16* pBh = g_kh + zoff;
    const __nv_bfloat16* pBl = g_kl + zoff;

    const int mw = (wid & 3) * 32;
    const int nw = (wid >> 2) * 64;

    float acc[2][8][4] = {};

    auto copy_chunk = [&](int kc, int stg) {
        const uint32_t s0 = sb + (uint32_t)stg * STAGE;
        const int k0  = kc * 16;
        const int row = t >> 4;
        const int c   = t & 15;
        const uint32_t so = (uint32_t)(row * 272 + c * 16);
        cp16(s0 + so,          pAh + (size_t)(k0 + row) * Wn + m0 + c * 8);
        cp16(s0 + OFF_AL + so, pAl + (size_t)(k0 + row) * Wn + m0 + c * 8);
        cp16(s0 + OFF_BH + so, pBh + (size_t)(k0 + row) * Wn + n0 + c * 8);
        cp16(s0 + OFF_BL + so, pBl + (size_t)(k0 + row) * Wn + n0 + c * 8);
    };

    auto compute = [&](int stg) {
        const uint32_t s0 = sb + (uint32_t)stg * STAGE;
        uint32_t ah[2][4], al[2][4];
        #pragma unroll
        for (int mt = 0; mt < 2; mt++) {
            int kk = (lane & 7) + ((lane >> 4) << 3);
            int mm = mw + mt * 16 + ((lane >> 3) & 1) * 8;
            uint32_t rel = (uint32_t)(kk * 272 + mm * 2);
            ldsm_x4_t(ah[mt], s0 + rel);
            ldsm_x4_t(al[mt], s0 + OFF_AL + rel);
        }
        #pragma unroll
        for (int np = 0; np < 4; np++) {
            int kk = (lane & 7) + ((lane >> 3) & 1) * 8;
            int nn = nw + np * 16 + ((lane >> 4) & 1) * 8;
            uint32_t rel = (uint32_t)(kk * 272 + nn * 2);
            uint32_t bh[4], bl[4];
            ldsm_x4_t(bh, s0 + OFF_BH + rel);
            ldsm_x4_t(bl, s0 + OFF_BL + rel);
            #pragma unroll
            for (int mt = 0; mt < 2; mt++) {
                #pragma unroll
                for (int h = 0; h < 2; h++) {
                    float* c = acc[mt][np * 2 + h];
                    mma16816(c, ah[mt], bh + 2 * h);
                    mma16816(c, ah[mt], bl + 2 * h);
                    mma16816(c, al[mt], bh + 2 * h);
                }
            }
        }
    };

    copy_chunk(0, 0);
    cp_commit();
    for (int kc = 0; kc < 16; kc++) {
        cp_wait<0>();        // drain chunk kc (only pending group)
        __syncthreads();     // chunk kc visible CTA-wide; prior compute done
        if (kc < 15) { copy_chunk(kc + 1, (kc + 1) & 1); cp_commit(); }
        compute(kc & 1);
    }

    const int g  = lane >> 2;
    const int tg = lane & 3;
    #pragma unroll
    for (int mt = 0; mt < 2; mt++) {
        const int r0 = m0 + mw + mt * 16 + g;
        #pragma unroll
        for (int nj = 0; nj < 8; nj++) {
            const int col = n0 + nw + nj * 8 + tg * 2;
            *reinterpret_cast<float2*>(g_attn + zoff + (size_t)r0 * Wn + col) =
                make_float2(acc[mt][nj][0], acc[mt][nj][1]);
            *reinterpret_cast<float2*>(g_attn + zoff + (size_t)(r0 + 8) * Wn + col) =
                make_float2(acc[mt][nj][2], acc[mt][nj][3]);
        }
    }
}

// ---------------------------------------------------------------------------
// Kernel B2: av GEMM. out[z,i,j] = sum_m attn[z,i,m] v[z,m,j].
// ---------------------------------------------------------------------------
__global__ void __launch_bounds__(256, 2) gemm_av_kernel(float* __restrict__ out)
{
    constexpr int APITCH = 48;
    constexpr int OFF_AL = 6144;
    constexpr int OFF_BH = 12288;
    constexpr int OFF_BL = 16640;
    constexpr int STAGE  = 20992;

    __shared__ __align__(16) char smem[2 * STAGE];
    const uint32_t sb = smem_to_u32(smem);

    const int t    = threadIdx.x;
    const int lane = t & 31;
    const int wid  = t >> 5;
    const int z    = blockIdx.y;
    const int m0   = (blockIdx.x & 1) * 128;
    const int n0   = (blockIdx.x >> 1) * 128;
    const size_t zoff = (size_t)z * HWn;

    const __nv_bfloat16* pAh = g_ah + zoff;
    const __nv_bfloat16* pAl = g_al + zoff;
    const __nv_bfloat16* pBh = g_vh + zoff;
    const __nv_bfloat16* pBl = g_vl + zoff;

    const int mw = (wid & 3) * 32;
    const int nw = (wid >> 2) * 64;

    float acc[2][8][4] = {};

    auto copy_chunk = [&](int kc, int stg) {
        const uint32_t s0 = sb + (uint32_t)stg * STAGE;
        const int k0 = kc * 16;
        {
            const int row = t >> 1;
            const int c   = t & 1;
            const uint32_t so = (uint32_t)(row * APITCH + c * 16);
            cp16(s0 + so,          pAh + (size_t)(m0 + row) * Wn + k0 + c * 8);
            cp16(s0 + OFF_AL + so, pAl + (size_t)(m0 + row) * Wn + k0 + c * 8);
        }
        {
            const int row = t >> 4;
            const int c   = t & 15;
            const uint32_t so = (uint32_t)(row * 272 + c * 16);
            cp16(s0 + OFF_BH + so, pBh + (size_t)(k0 + row) * Wn + n0 + c * 8);
            cp16(s0 + OFF_BL + so, pBl + (size_t)(k0 + row) * Wn + n0 + c * 8);
        }
    };

    auto compute = [&](int stg) {
        const uint32_t s0 = sb + (uint32_t)stg * STAGE;
        uint32_t ah[2][4], al[2][4];
        #pragma unroll
        for (int mt = 0; mt < 2; mt++) {
            int mm = mw + mt * 16 + (lane & 15);
            int kk = ((lane >> 4) & 1) * 8;
            uint32_t rel = (uint32_t)(mm * APITCH + kk * 2);
            ldsm_x4(ah[mt], s0 + rel);
            ldsm_x4(al[mt], s0 + OFF_AL + rel);
        }
        #pragma unroll
        for (int np = 0; np < 4; np++) {
            int kk = (lane & 7) + ((lane >> 3) & 1) * 8;
            int nn = nw + np * 16 + ((lane >> 4) & 1) * 8;
            uint32_t rel = (uint32_t)(kk * 272 + nn * 2);
            uint32_t bh[4], bl[4];
            ldsm_x4_t(bh, s0 + OFF_BH + rel);
            ldsm_x4_t(bl, s0 + OFF_BL + rel);
            #pragma unroll
            for (int mt = 0; mt < 2; mt++) {
                #pragma unroll
                for (int h = 0; h < 2; h++) {
                    float* c = acc[mt][np * 2 + h];
                    mma16816(c, ah[mt], bh + 2 * h);
                    mma16816(c, ah[mt], bl + 2 * h);
                    mma16816(c, al[mt], bh + 2 * h);
                }
            }
        }
    };

    copy_chunk(0, 0);
    cp_commit();
    for (int kc = 0; kc < 16; kc++) {
        cp_wait<0>();
        __syncthreads();
        if (kc < 15) { copy_chunk(kc + 1, (kc + 1) & 1); cp_commit(); }
        compute(kc & 1);
    }

    const int g  = lane >> 2;
    const int tg = lane & 3;
    #pragma unroll
    for (int mt = 0; mt < 2; mt++) {
        const int r0 = m0 + mw + mt * 16 + g;
        #pragma unroll
        for (int nj = 0; nj < 8; nj++) {
            const int col = n0 + nw + nj * 8 + tg * 2;
            *reinterpret_cast<float2*>(out + zoff + (size_t)r0 * Wn + col) =
                make_float2(acc[mt][nj][0], acc[mt][nj][1]);
            *reinterpret_cast<float2*>(out + zoff + (size_t)(r0 + 8) * Wn + col) =
                make_float2(acc[mt][nj][2], acc[mt][nj][3]);
        }
    }
}

// ---------------------------------------------------------------------------
// Kernel C: softmax over channel axis (fp32 in, bf16 hi/lo out)
// ---------------------------------------------------------------------------
__global__ void __launch_bounds__(256) softmax_split_kernel()
{
    const int idx = blockIdx.x * 256 + threadIdx.x;   // 0 .. B*HW-1
    const int b   = idx >> 16;
    const int ij  = idx & 65535;
    const size_t base = (size_t)b * CHWn + ij;

    float v[64];
    float mx = -INFINITY;
    #pragma unroll
    for (int c = 0; c < 64; c++) {
        v[c] = g_attn[base + (size_t)c * HWn];
        mx = fmaxf(mx, v[c]);
    }
    float s = 0.0f;
    #pragma unroll
    for (int c = 0; c < 64; c++) {
        v[c] = expf(v[c] - mx);
        s += v[c];
    }
    const float inv = 1.0f / s;
    #pragma unroll
    for (int c = 0; c < 64; c++) {
        float p = v[c] * inv;
        __nv_bfloat16 hi, lo;
        split_bf16(p, hi, lo);
        g_ah[base + (size_t)c * HWn] = hi;
        g_al[base + (size_t)c * HWn] = lo;
    }
}

// ---------------------------------------------------------------------------
// Launch — no dynamic smem, no attribute calls, plain default-stream launches.
// ---------------------------------------------------------------------------
extern "C" void kernel_launch(void* const* d_in, const int* in_sizes, int n_in,
                              void* d_out, int out_size)
{
    const float* x  = (const float*)d_in[0];
    const float* Wq = (const float*)d_in[1];
    const float* bq = (const float*)d_in[2];
    const float* Wk = (const float*)d_in[3];
    const float* bk = (const float*)d_in[4];
    const float* Wv = (const float*)d_in[5];
    const float* bv = (const float*)d_in[6];
    float* out = (float*)d_out;

    // 0) split weights to bf16 hi/lo (tiny)
    wsplit_kernel<<<48, 256>>>(Wq, Wk, Wv);

    // 1) q,k,v = 1x1 conv(x) on tensor cores, bf16 hi/lo out in [z][h][w]
    qkv_mma_kernel<<<dim3(HWn / 64, Bn), 256>>>(x, bq, bk, bv);

    // 2) attn logits: attn[z,i,j] = sum_h q[z,h,i] k[z,h,j]
    gemm_qtk_kernel<<<dim3(4, NZ), 256>>>();

    // 3) softmax over channels, emit bf16 hi/lo ([i][m] row-major for next GEMM)
    softmax_split_kernel<<<(Bn * HWn) / 256, 256>>>();

    // 4) out[z,i,j] = sum_m attn[z,i,m] v[z,m,j]
    gemm_av_kernel<<<dim3(4, NZ), 256>>>(out);
}

// round 12
// speedup vs baseline: 2.1223x; 1.0034x over previous
#include <cuda_runtime.h>
#include <cuda_bf16.h>
#include <math.h>
#include <stdint.h>

// ---------------------------------------------------------------------------
// Problem constants
// ---------------------------------------------------------------------------
static constexpr int Bn = 8, Cn = 64, Hn = 256, Wn = 256;
static constexpr int HWn  = Hn * Wn;       // 65536
static constexpr int CHWn = Cn * HWn;      // 4194304
static constexpr int NZ   = Bn * Cn;       // 512
static constexpr int NTOT = 33554432;      // B*C*H*W

// ---------------------------------------------------------------------------
// Scratch (device globals: allocation-free contract)
// ---------------------------------------------------------------------------
__device__ __nv_bfloat16 g_qh[NTOT], g_ql[NTOT];
__device__ __nv_bfloat16 g_kh[NTOT], g_kl[NTOT];
__device__ __nv_bfloat16 g_vh[NTOT], g_vl[NTOT];
__device__ float         g_attn[NTOT];                 // fp32 logits [z][i][j]
__device__ __nv_bfloat16 g_ah[NTOT], g_al[NTOT];       // softmaxed attn split

// ---------------------------------------------------------------------------
// PTX helpers — sm_80-era features only (compile clean at .target sm_103)
// ---------------------------------------------------------------------------
__device__ __forceinline__ uint32_t smem_to_u32(const void* p) {
    uint32_t a;
    asm("{ .reg .u64 t; cvta.to.shared.u64 t, %1; cvt.u32.u64 %0, t; }"
        : "=r"(a) : "l"(p));
    return a;
}

__device__ __forceinline__ void cp16(uint32_t s, const void* g) {
    asm volatile("cp.async.cg.shared.global [%0], [%1], 16;"
                 :: "r"(s), "l"(g) : "memory");
}
__device__ __forceinline__ void cp_commit() {
    asm volatile("cp.async.commit_group;" ::: "memory");
}
template <int N>
__device__ __forceinline__ void cp_wait() {
    asm volatile("cp.async.wait_group %0;" :: "n"(N) : "memory");
}

__device__ __forceinline__ void ldsm_x4(uint32_t* r, uint32_t addr) {
    asm volatile("ldmatrix.sync.aligned.m8n8.x4.shared.b16 {%0,%1,%2,%3}, [%4];"
                 : "=r"(r[0]), "=r"(r[1]), "=r"(r[2]), "=r"(r[3]) : "r"(addr));
}
__device__ __forceinline__ void ldsm_x4_t(uint32_t* r, uint32_t addr) {
    asm volatile("ldmatrix.sync.aligned.m8n8.x4.trans.shared.b16 {%0,%1,%2,%3}, [%4];"
                 : "=r"(r[0]), "=r"(r[1]), "=r"(r[2]), "=r"(r[3]) : "r"(addr));
}

__device__ __forceinline__ void mma16816(float* c, const uint32_t* a, const uint32_t* b) {
    asm volatile(
        "mma.sync.aligned.m16n8k16.row.col.f32.bf16.bf16.f32 "
        "{%0,%1,%2,%3}, {%4,%5,%6,%7}, {%8,%9}, {%0,%1,%2,%3};"
        : "+f"(c[0]), "+f"(c[1]), "+f"(c[2]), "+f"(c[3])
        : "r"(a[0]), "r"(a[1]), "r"(a[2]), "r"(a[3]), "r"(b[0]), "r"(b[1]));
}

__device__ __forceinline__ void split_bf16(float x, __nv_bfloat16& hi, __nv_bfloat16& lo) {
    hi = __float2bfloat16(x);
    lo = __float2bfloat16(x - __bfloat162float(hi));
}

// ---------------------------------------------------------------------------
// Kernel A: tensor-core 1x1 conv. Per CTA: batch b, 64 pixels, all 3 matrices.
// M=o(64) x N=p(64) x K=c(64).
//   A = W[o][c] row-major, pitch 72 -> non-trans ldmatrix (W split inline)
//   B = x[c][p] K-major,  pitch 72 -> trans ldmatrix
// mma issued TERM-MAJOR so consecutive mma hit different accumulators.
// ---------------------------------------------------------------------------
__global__ void __launch_bounds__(256) qkv_mma_kernel(
    const float* __restrict__ x,
    const float* __restrict__ Wq, const float* __restrict__ bq,
    const float* __restrict__ Wk, const float* __restrict__ bk,
    const float* __restrict__ Wv, const float* __restrict__ bv)
{
    constexpr int XP = 72;   // pitch in elems (144 B)
    constexpr int WP = 72;

    __shared__ __align__(16) __nv_bfloat16 Xh[64 * XP], Xl[64 * XP];
    __shared__ __align__(16) __nv_bfloat16 Wh[64 * WP], Wl[64 * WP];

    const uint32_t sXh = smem_to_u32(Xh), sXl = smem_to_u32(Xl);
    const uint32_t sWh = smem_to_u32(Wh), sWl = smem_to_u32(Wl);

    const int t    = threadIdx.x;
    const int lane = t & 31;
    const int wid  = t >> 5;
    const int b    = blockIdx.y;
    const int p0   = blockIdx.x * 64;

    // --- stage x tile [c=64][p=64], split to hi/lo ---
    {
        const int c  = t >> 2;          // 0..63
        const int pg = (t & 3) * 16;    // 0,16,32,48
        const float* xrow = x + ((size_t)(b * Cn + c)) * HWn + p0 + pg;
        __nv_bfloat16 hb[16], lb[16];
        #pragma unroll
        for (int j = 0; j < 16; j += 4) {
            float4 v4 = *reinterpret_cast<const float4*>(xrow + j);
            split_bf16(v4.x, hb[j + 0], lb[j + 0]);
            split_bf16(v4.y, hb[j + 1], lb[j + 1]);
            split_bf16(v4.z, hb[j + 2], lb[j + 2]);
            split_bf16(v4.w, hb[j + 3], lb[j + 3]);
        }
        *reinterpret_cast<uint4*>(&Xh[c * XP + pg])     = reinterpret_cast<uint4*>(hb)[0];
        *reinterpret_cast<uint4*>(&Xh[c * XP + pg + 8]) = reinterpret_cast<uint4*>(hb)[1];
        *reinterpret_cast<uint4*>(&Xl[c * XP + pg])     = reinterpret_cast<uint4*>(lb)[0];
        *reinterpret_cast<uint4*>(&Xl[c * XP + pg + 8]) = reinterpret_cast<uint4*>(lb)[1];
    }

    const float* Wmats[3]  = {Wq, Wk, Wv};
    const float* biases[3] = {bq, bk, bv};
    __nv_bfloat16* outs_hi[3] = {g_qh, g_kh, g_vh};
    __nv_bfloat16* outs_lo[3] = {g_ql, g_kl, g_vl};

    const int mw = (wid & 3) * 16;   // o-offset of warp
    const int nw = (wid >> 2) * 32;  // p-offset of warp
    const int g  = lane >> 2;
    const int tg = lane & 3;

    for (int m = 0; m < 3; m++) {
        __syncthreads();   // prior compute done before W overwrite
        {   // stage W[o][c] hi/lo: load fp32, split inline (wsplit fused)
            const int o  = t >> 2;
            const int cg = (t & 3) * 16;
            const float* wsrc = Wmats[m] + o * 64 + cg;
            __nv_bfloat16 hb[16], lb[16];
            #pragma unroll
            for (int j = 0; j < 16; j += 4) {
                float4 v4 = *reinterpret_cast<const float4*>(wsrc + j);
                split_bf16(v4.x, hb[j + 0], lb[j + 0]);
                split_bf16(v4.y, hb[j + 1], lb[j + 1]);
                split_bf16(v4.z, hb[j + 2], lb[j + 2]);
                split_bf16(v4.w, hb[j + 3], lb[j + 3]);
            }
            *reinterpret_cast<uint4*>(&Wh[o * WP + cg])     = reinterpret_cast<uint4*>(hb)[0];
            *reinterpret_cast<uint4*>(&Wh[o * WP + cg + 8]) = reinterpret_cast<uint4*>(hb)[1];
            *reinterpret_cast<uint4*>(&Wl[o * WP + cg])     = reinterpret_cast<uint4*>(lb)[0];
            *reinterpret_cast<uint4*>(&Wl[o * WP + cg + 8]) = reinterpret_cast<uint4*>(lb)[1];
        }
        __syncthreads();   // W + X visible (covers X stores on m==0)

        float acc[4][4] = {};
        #pragma unroll
        for (int ks = 0; ks < 4; ks++) {
            uint32_t ah[4], al[4];
            {   // A = W rows (o), non-trans
                int mm = mw + (lane & 15);
                int kk = ks * 16 + ((lane >> 4) & 1) * 8;
                uint32_t rel = (uint32_t)((mm * WP + kk) * 2);
                ldsm_x4(ah, sWh + rel);
                ldsm_x4(al, sWl + rel);
            }
            uint32_t bh[2][4], bl[2][4];
            #pragma unroll
            for (int np = 0; np < 2; np++) {
                int kk = ks * 16 + (lane & 7) + ((lane >> 3) & 1) * 8;
                int nn = nw + np * 16 + ((lane >> 4) & 1) * 8;
                uint32_t rel = (uint32_t)((kk * XP + nn) * 2);
                ldsm_x4_t(bh[np], sXh + rel);
                ldsm_x4_t(bl[np], sXl + rel);
            }
            // term-major: consecutive mma target different accumulators
            #pragma unroll
            for (int np = 0; np < 2; np++)
                #pragma unroll
                for (int h = 0; h < 2; h++)
                    mma16816(acc[np * 2 + h], ah, bh[np] + 2 * h);
            #pragma unroll
            for (int np = 0; np < 2; np++)
                #pragma unroll
                for (int h = 0; h < 2; h++)
                    mma16816(acc[np * 2 + h], ah, bl[np] + 2 * h);
            #pragma unroll
            for (int np = 0; np < 2; np++)
                #pragma unroll
                for (int h = 0; h < 2; h++)
                    mma16816(acc[np * 2 + h], al, bh[np] + 2 * h);
        }

        // epilogue: bias add, split, store bf16x2 pairs (consecutive pixels)
        const float* bias = biases[m];
        const float bo0 = bias[mw + g];
        const float bo1 = bias[mw + 8 + g];
        __nv_bfloat16* dh = outs_hi[m];
        __nv_bfloat16* dl = outs_lo[m];
        const size_t row0 = (size_t)(b * Cn + mw + g) * HWn + p0;
        const size_t row1 = (size_t)(b * Cn + mw + 8 + g) * HWn + p0;
        #pragma unroll
        for (int nj = 0; nj < 4; nj++) {
            const int p = nw + nj * 8 + tg * 2;
            __nv_bfloat16 h0, l0, h1, l1;
            split_bf16(acc[nj][0] + bo0, h0, l0);
            split_bf16(acc[nj][1] + bo0, h1, l1);
            __nv_bfloat162 hp, lp;
            hp.x = h0; hp.y = h1; lp.x = l0; lp.y = l1;
            *reinterpret_cast<__nv_bfloat162*>(dh + row0 + p) = hp;
            *reinterpret_cast<__nv_bfloat162*>(dl + row0 + p) = lp;
            split_bf16(acc[nj][2] + bo1, h0, l0);
            split_bf16(acc[nj][3] + bo1, h1, l1);
            hp.x = h0; hp.y = h1; lp.x = l0; lp.y = l1;
            *reinterpret_cast<__nv_bfloat162*>(dh + row1 + p) = hp;
            *reinterpret_cast<__nv_bfloat162*>(dl + row1 + p) = lp;
        }
    }
}

// ---------------------------------------------------------------------------
// Kernel B1: qtk GEMM. attn[z,i,j] = sum_h q[z,h,i] k[z,h,j].
// 128x128 CTA tile, K-chunks of 16, cp.async double-buffered static smem.
// Term-major mma ordering (acc reuse distance = 4 mma).
// ---------------------------------------------------------------------------
__global__ void __launch_bounds__(256, 2) gemm_qtk_kernel()
{
    constexpr int OFF_AL = 4352;      // A tile: [16][136] bf16 = 4352 B
    constexpr int OFF_BH = 8704;
    constexpr int OFF_BL = 13056;
    constexpr int STAGE  = 17408;

    __shared__ __align__(16) char smem[2 * STAGE];
    const uint32_t sb = smem_to_u32(smem);

    const int t    = threadIdx.x;
    const int lane = t & 31;
    const int wid  = t >> 5;
    const int z    = blockIdx.y;
    const int m0   = (blockIdx.x & 1) * 128;
    const int n0   = (blockIdx.x >> 1) * 128;
    const size_t zoff = (size_t)z * HWn;

    const __nv_bfloat16* pAh = g_qh + zoff;
    const __nv_bfloat16* pAl = g_ql + zoff;
    const __nv_bfloat16* pBh = g_kh + zoff;
    const __nv_bfloat16* pBl = g_kl + zoff;

    const int mw = (wid & 3) * 32;
    const int nw = (wid >> 2) * 64;

    float acc[2][8][4] = {};

    auto copy_chunk = [&](int kc, int stg) {
        const uint32_t s0 = sb + (uint32_t)stg * STAGE;
        const int k0  = kc * 16;
        const int row = t >> 4;
        const int c   = t & 15;
        const uint32_t so = (uint32_t)(row * 272 + c * 16);
        cp16(s0 + so,          pAh + (size_t)(k0 + row) * Wn + m0 + c * 8);
        cp16(s0 + OFF_AL + so, pAl + (size_t)(k0 + row) * Wn + m0 + c * 8);
        cp16(s0 + OFF_BH + so, pBh + (size_t)(k0 + row) * Wn + n0 + c * 8);
        cp16(s0 + OFF_BL + so, pBl + (size_t)(k0 + row) * Wn + n0 + c * 8);
    };

    auto compute = [&](int stg) {
        const uint32_t s0 = sb + (uint32_t)stg * STAGE;
        uint32_t ah[2][4], al[2][4];
        #pragma unroll
        for (int mt = 0; mt < 2; mt++) {
            int kk = (lane & 7) + ((lane >> 4) << 3);
            int mm = mw + mt * 16 + ((lane >> 3) & 1) * 8;
            uint32_t rel = (uint32_t)(kk * 272 + mm * 2);
            ldsm_x4_t(ah[mt], s0 + rel);
            ldsm_x4_t(al[mt], s0 + OFF_AL + rel);
        }
        #pragma unroll
        for (int np = 0; np < 4; np++) {
            int kk = (lane & 7) + ((lane >> 3) & 1) * 8;
            int nn = nw + np * 16 + ((lane >> 4) & 1) * 8;
            uint32_t rel = (uint32_t)(kk * 272 + nn * 2);
            uint32_t bh[4], bl[4];
            ldsm_x4_t(bh, s0 + OFF_BH + rel);
            ldsm_x4_t(bl, s0 + OFF_BL + rel);
            // term-major: acc reuse distance = 4 mma
            #pragma unroll
            for (int mt = 0; mt < 2; mt++)
                #pragma unroll
                for (int h = 0; h < 2; h++)
                    mma16816(acc[mt][np * 2 + h], ah[mt], bh + 2 * h);
            #pragma unroll
            for (int mt = 0; mt < 2; mt++)
                #pragma unroll
                for (int h = 0; h < 2; h++)
                    mma16816(acc[mt][np * 2 + h], ah[mt], bl + 2 * h);
            #pragma unroll
            for (int mt = 0; mt < 2; mt++)
                #pragma unroll
                for (int h = 0; h < 2; h++)
                    mma16816(acc[mt][np * 2 + h], al[mt], bh + 2 * h);
        }
    };

    copy_chunk(0, 0);
    cp_commit();
    for (int kc = 0; kc < 16; kc++) {
        cp_wait<0>();        // drain chunk kc (only pending group)
        __syncthreads();     // chunk kc visible CTA-wide; prior compute done
        if (kc < 15) { copy_chunk(kc + 1, (kc + 1) & 1); cp_commit(); }
        compute(kc & 1);
    }

    const int g  = lane >> 2;
    const int tg = lane & 3;
    #pragma unroll
    for (int mt = 0; mt < 2; mt++) {
        const int r0 = m0 + mw + mt * 16 + g;
        #pragma unroll
        for (int nj = 0; nj < 8; nj++) {
            const int col = n0 + nw + nj * 8 + tg * 2;
            *reinterpret_cast<float2*>(g_attn + zoff + (size_t)r0 * Wn + col) =
                make_float2(acc[mt][nj][0], acc[mt][nj][1]);
            *reinterpret_cast<float2*>(g_attn + zoff + (size_t)(r0 + 8) * Wn + col) =
                make_float2(acc[mt][nj][2], acc[mt][nj][3]);
        }
    }
}

// ---------------------------------------------------------------------------
// Kernel B2: av GEMM. out[z,i,j] = sum_m attn[z,i,m] v[z,m,j].
// ---------------------------------------------------------------------------
__global__ void __launch_bounds__(256, 2) gemm_av_kernel(float* __restrict__ out)
{
    constexpr int APITCH = 48;
    constexpr int OFF_AL = 6144;
    constexpr int OFF_BH = 12288;
    constexpr int OFF_BL = 16640;
    constexpr int STAGE  = 20992;

    __shared__ __align__(16) char smem[2 * STAGE];
    const uint32_t sb = smem_to_u32(smem);

    const int t    = threadIdx.x;
    const int lane = t & 31;
    const int wid  = t >> 5;
    const int z    = blockIdx.y;
    const int m0   = (blockIdx.x & 1) * 128;
    const int n0   = (blockIdx.x >> 1) * 128;
    const size_t zoff = (size_t)z * HWn;

    const __nv_bfloat16* pAh = g_ah + zoff;
    const __nv_bfloat16* pAl = g_al + zoff;
    const __nv_bfloat16* pBh = g_vh + zoff;
    const __nv_bfloat16* pBl = g_vl + zoff;

    const int mw = (wid & 3) * 32;
    const int nw = (wid >> 2) * 64;

    float acc[2][8][4] = {};

    auto copy_chunk = [&](int kc, int stg) {
        const uint32_t s0 = sb + (uint32_t)stg * STAGE;
        const int k0 = kc * 16;
        {
            const int row = t >> 1;
            const int c   = t & 1;
            const uint32_t so = (uint32_t)(row * APITCH + c * 16);
            cp16(s0 + so,          pAh + (size_t)(m0 + row) * Wn + k0 + c * 8);
            cp16(s0 + OFF_AL + so, pAl + (size_t)(m0 + row) * Wn + k0 + c * 8);
        }
        {
            const int row = t >> 4;
            const int c   = t & 15;
            const uint32_t so = (uint32_t)(row * 272 + c * 16);
            cp16(s0 + OFF_BH + so, pBh + (size_t)(k0 + row) * Wn + n0 + c * 8);
            cp16(s0 + OFF_BL + so, pBl + (size_t)(k0 + row) * Wn + n0 + c * 8);
        }
    };

    auto compute = [&](int stg) {
        const uint32_t s0 = sb + (uint32_t)stg * STAGE;
        uint32_t ah[2][4], al[2][4];
        #pragma unroll
        for (int mt = 0; mt < 2; mt++) {
            int mm = mw + mt * 16 + (lane & 15);
            int kk = ((lane >> 4) & 1) * 8;
            uint32_t rel = (uint32_t)(mm * APITCH + kk * 2);
            ldsm_x4(ah[mt], s0 + rel);
            ldsm_x4(al[mt], s0 + OFF_AL + rel);
        }
        #pragma unroll
        for (int np = 0; np < 4; np++) {
            int kk = (lane & 7) + ((lane >> 3) & 1) * 8;
            int nn = nw + np * 16 + ((lane >> 4) & 1) * 8;
            uint32_t rel = (uint32_t)(kk * 272 + nn * 2);
            uint32_t bh[4], bl[4];
            ldsm_x4_t(bh, s0 + OFF_BH + rel);
            ldsm_x4_t(bl, s0 + OFF_BL + rel);
            // term-major: acc reuse distance = 4 mma
            #pragma unroll
            for (int mt = 0; mt < 2; mt++)
                #pragma unroll
                for (int h = 0; h < 2; h++)
                    mma16816(acc[mt][np * 2 + h], ah[mt], bh + 2 * h);
            #pragma unroll
            for (int mt = 0; mt < 2; mt++)
                #pragma unroll
                for (int h = 0; h < 2; h++)
                    mma16816(acc[mt][np * 2 + h], ah[mt], bl + 2 * h);
            #pragma unroll
            for (int mt = 0; mt < 2; mt++)
                #pragma unroll
                for (int h = 0; h < 2; h++)
                    mma16816(acc[mt][np * 2 + h], al[mt], bh + 2 * h);
        }
    };

    copy_chunk(0, 0);
    cp_commit();
    for (int kc = 0; kc < 16; kc++) {
        cp_wait<0>();
        __syncthreads();
        if (kc < 15) { copy_chunk(kc + 1, (kc + 1) & 1); cp_commit(); }
        compute(kc & 1);
    }

    const int g  = lane >> 2;
    const int tg = lane & 3;
    #pragma unroll
    for (int mt = 0; mt < 2; mt++) {
        const int r0 = m0 + mw + mt * 16 + g;
        #pragma unroll
        for (int nj = 0; nj < 8; nj++) {
            const int col = n0 + nw + nj * 8 + tg * 2;
            *reinterpret_cast<float2*>(out + zoff + (size_t)r0 * Wn + col) =
                make_float2(acc[mt][nj][0], acc[mt][nj][1]);
            *reinterpret_cast<float2*>(out + zoff + (size_t)(r0 + 8) * Wn + col) =
                make_float2(acc[mt][nj][2], acc[mt][nj][3]);
        }
    }
}

// ---------------------------------------------------------------------------
// Kernel C: softmax over channel axis (fp32 in, bf16 hi/lo out)
// ---------------------------------------------------------------------------
__global__ void __launch_bounds__(256) softmax_split_kernel()
{
    const int idx = blockIdx.x * 256 + threadIdx.x;   // 0 .. B*HW-1
    const int b   = idx >> 16;
    const int ij  = idx & 65535;
    const size_t base = (size_t)b * CHWn + ij;

    float v[64];
    float mx = -INFINITY;
    #pragma unroll
    for (int c = 0; c < 64; c++) {
        v[c] = g_attn[base + (size_t)c * HWn];
        mx = fmaxf(mx, v[c]);
    }
    float s = 0.0f;
    #pragma unroll
    for (int c = 0; c < 64; c++) {
        v[c] = expf(v[c] - mx);
        s += v[c];
    }
    const float inv = 1.0f / s;
    #pragma unroll
    for (int c = 0; c < 64; c++) {
        float p = v[c] * inv;
        __nv_bfloat16 hi, lo;
        split_bf16(p, hi, lo);
        g_ah[base + (size_t)c * HWn] = hi;
        g_al[base + (size_t)c * HWn] = lo;
    }
}

// ---------------------------------------------------------------------------
// Launch — no dynamic smem, no attribute calls, plain default-stream launches.
// ---------------------------------------------------------------------------
extern "C" void kernel_launch(void* const* d_in, const int* in_sizes, int n_in,
                              void* d_out, int out_size)
{
    const float* x  = (const float*)d_in[0];
    const float* Wq = (const float*)d_in[1];
    const float* bq = (const float*)d_in[2];
    const float* Wk = (const float*)d_in[3];
    const float* bk = (const float*)d_in[4];
    const float* Wv = (const float*)d_in[5];
    const float* bv = (const float*)d_in[6];
    float* out = (float*)d_out;

    // 1) q,k,v = 1x1 conv(x) on tensor cores (W split fused), hi/lo [z][h][w]
    qkv_mma_kernel<<<dim3(HWn / 64, Bn), 256>>>(x, Wq, bq, Wk, bk, Wv, bv);

    // 2) attn logits: attn[z,i,j] = sum_h q[z,h,i] k[z,h,j]
    gemm_qtk_kernel<<<dim3(4, NZ), 256>>>();

    // 3) softmax over channels, emit bf16 hi/lo ([i][m] row-major for next GEMM)
    softmax_split_kernel<<<(Bn * HWn) / 256, 256>>>();

    // 4) out[z,i,j] = sum_m attn[z,i,m] v[z,m,j]
    gemm_av_kernel<<<dim3(4, NZ), 256>>>(out);
}